// round 3
// baseline (speedup 1.0000x reference)
#include <cuda_runtime.h>
#include <math.h>

typedef unsigned long long u64;

// ---------------- constants ----------------
#define B_  64
#define S_  50
#define T_  50
#define R_  2
#define H_  256
#define NU_ (B_*S_)          // 3200
#define NR_ (B_*R_)          // 128
#define MU_ (T_*NU_)         // 160000
#define MR_ (T_*NR_)         // 6400
#define MC_ (S_*B_)          // 3200
#define TAB_N (B_*(S_+1)*H_) // 835584

// output offsets (f32 elements)
#define OFF_CTXOUT   0
#define OFF_CTXHID   819200
#define OFF_RESPOUT  835584
#define OFF_RESPHID  2473984
#define OFF_SPKEMB   2506752
#define OFF_MASK     3342336

// ---------------- static device scratch ----------------
__device__ float g_tables[TAB_N];
__device__ float g_GIu[(size_t)MU_*768];
__device__ float g_GIc[(size_t)MC_*768];
__device__ float g_GIs[(size_t)MC_*768];
__device__ float g_GIr[(size_t)MR_*768];
__device__ float g_hu[NU_*H_];
__device__ float g_hc[B_*H_];
__device__ float g_hr[NR_*H_];
__device__ float g_hspk[B_*(S_+1)*H_];
__device__ float g_ctxin[MC_*2*H_];
__device__ float g_WTu_i[H_*768],  g_WTu_h[H_*768];
__device__ float g_WTc_i[2*H_*768],g_WTc_h[H_*768];
__device__ float g_WTr_i[H_*768],  g_WTr_h[H_*768];
__device__ float g_WTs_i[H_*768],  g_WTs_h[H_*768];
__device__ int   g_toku[MU_];
__device__ int   g_tokr[MR_];
__device__ int   g_present[B_*(S_+1)];

// ---------------- f32x2 / cp.async helpers ----------------
__device__ __forceinline__ u64 pack2(float lo, float hi) {
    u64 r; asm("mov.b64 %0, {%1,%2};" : "=l"(r) : "f"(lo), "f"(hi)); return r;
}
__device__ __forceinline__ void unpack2(u64 a, float& lo, float& hi) {
    asm("mov.b64 {%0,%1}, %2;" : "=f"(lo), "=f"(hi) : "l"(a));
}
__device__ __forceinline__ u64 ffma2(u64 a, u64 b, u64 c) {
    u64 d; asm("fma.rn.f32x2 %0, %1, %2, %3;" : "=l"(d) : "l"(a), "l"(b), "l"(c)); return d;
}
__device__ __forceinline__ void cp_async16(float* dst_smem, const float* src) {
    unsigned sa = (unsigned)__cvta_generic_to_shared(dst_smem);
    asm volatile("cp.async.ca.shared.global [%0], [%1], 16;" :: "r"(sa), "l"(src));
}
__device__ __forceinline__ void cp_commit() { asm volatile("cp.async.commit_group;"); }
template<int N> __device__ __forceinline__ void cp_wait() { asm volatile("cp.async.wait_group %0;" :: "n"(N)); }

// ---------------- MT19937 (NumPy-exact), 256-thread body ----------------
__device__ __forceinline__ unsigned mt_twist_fn(unsigned u, unsigned v) {
    unsigned y = (u & 0x80000000u) | (v & 0x7fffffffu);
    return (y >> 1) ^ ((v & 1u) ? 0x9908b0dfu : 0u);
}
__device__ __forceinline__ unsigned mt_temper(unsigned y) {
    y ^= y >> 11; y ^= (y << 7) & 0x9d2c5680u; y ^= (y << 15) & 0xefc60000u; y ^= y >> 18;
    return y;
}
__device__ void mt_body(float* __restrict__ tables, unsigned* bufA, unsigned* bufB) {
    const int tid = threadIdx.x;
    if (tid == 0) {
        unsigned s = 1u; bufA[0] = s;
        for (int i = 1; i < 624; i++) { s = 1812433253u * (s ^ (s >> 30)) + (unsigned)i; bufA[i] = s; }
    }
    __syncthreads();
    unsigned* cur = bufA; unsigned* nxt = bufB;
    const int NTW = (2*TAB_N + 623) / 624;   // 2679
    for (int tw = 0; tw < NTW; tw++) {
        if (tid < 227) nxt[tid] = cur[tid + 397] ^ mt_twist_fn(cur[tid], cur[tid + 1]);
        __syncthreads();
        if (tid < 227) { int i = 227 + tid; nxt[i] = nxt[i - 227] ^ mt_twist_fn(cur[i], cur[i + 1]); }
        __syncthreads();
        if (tid < 170) {
            int i = 454 + tid;
            unsigned v = (i == 623) ? nxt[0] : cur[i + 1];
            nxt[i] = nxt[i - 227] ^ mt_twist_fn(cur[i], v);
        }
        __syncthreads();
        for (int o = tid; o < 312; o += 256) {
            int outIdx = tw * 312 + o;
            if (outIdx < TAB_N) {
                unsigned a  = mt_temper(nxt[2*o])   >> 5;
                unsigned bv = mt_temper(nxt[2*o+1]) >> 6;
                tables[outIdx] = (float)(((double)a * 67108864.0 + (double)bv) * (1.0 / 9007199254740992.0));
            }
        }
        __syncthreads();
        unsigned* t2 = cur; cur = nxt; nxt = t2;
    }
}

// ---------------- GEMM body (as R2): BM=BN=128, BK=16, 8x8/thread, FFMA2 ----------------
__device__ __forceinline__ void gemm_body(
    const float* __restrict__ A, const int* __restrict__ toks, const float* __restrict__ emb,
    const float* __restrict__ BT, const float* __restrict__ bias, float* __restrict__ C,
    int m0, int n0, int K, float* As, float* Bs)
{
    const int tid  = threadIdx.x;
    const int arow = tid >> 2;
    const int akc  = (tid & 3) << 2;
    const int bk   = tid >> 4;
    const int bc   = (tid & 15) << 3;
    const int tr   = tid >> 4;
    const int tc   = tid & 15;

    const float* arp0;
    const float* arp1;
    {
        int gm0 = m0 + arow, gm1 = m0 + arow + 64;
        arp0 = toks ? (emb + (size_t)__ldg(toks + gm0) * K) : (A + (size_t)gm0 * K);
        arp1 = toks ? (emb + (size_t)__ldg(toks + gm1) * K) : (A + (size_t)gm1 * K);
    }
    float4 ra0 = *(const float4*)(arp0 + akc);
    float4 ra1 = *(const float4*)(arp1 + akc);
    float4 rb0 = *(const float4*)(BT + (size_t)bk * 768 + n0 + bc);
    float4 rb1 = *(const float4*)(BT + (size_t)bk * 768 + n0 + bc + 4);
    {
        As[(akc+0)*128 + arow] = ra0.x; As[(akc+1)*128 + arow] = ra0.y;
        As[(akc+2)*128 + arow] = ra0.z; As[(akc+3)*128 + arow] = ra0.w;
        As[(akc+0)*128 + arow+64] = ra1.x; As[(akc+1)*128 + arow+64] = ra1.y;
        As[(akc+2)*128 + arow+64] = ra1.z; As[(akc+3)*128 + arow+64] = ra1.w;
        *(float4*)(Bs + bk*128 + bc)     = rb0;
        *(float4*)(Bs + bk*128 + bc + 4) = rb1;
    }
    __syncthreads();

    u64 acc[8][4];
    #pragma unroll
    for (int i = 0; i < 8; i++)
        #pragma unroll
        for (int j = 0; j < 4; j++) acc[i][j] = 0ull;

    int buf = 0;
    for (int k0 = 16; k0 <= K; k0 += 16) {
        const bool more = (k0 < K);
        if (more) {
            ra0 = *(const float4*)(arp0 + k0 + akc);
            ra1 = *(const float4*)(arp1 + k0 + akc);
            rb0 = *(const float4*)(BT + (size_t)(k0 + bk) * 768 + n0 + bc);
            rb1 = *(const float4*)(BT + (size_t)(k0 + bk) * 768 + n0 + bc + 4);
        }
        const float* Asb = As + buf * 2048;
        const float* Bsb = Bs + buf * 2048;
        #pragma unroll
        for (int kk = 0; kk < 16; kk++) {
            float4 av0 = *(const float4*)(Asb + kk*128 + tr*8);
            float4 av1 = *(const float4*)(Asb + kk*128 + tr*8 + 4);
            u64 bb0 = *(const u64*)(Bsb + kk*128 + tc*4);
            u64 bb1 = *(const u64*)(Bsb + kk*128 + tc*4 + 2);
            u64 bb2 = *(const u64*)(Bsb + kk*128 + 64 + tc*4);
            u64 bb3 = *(const u64*)(Bsb + kk*128 + 64 + tc*4 + 2);
            float av[8] = {av0.x, av0.y, av0.z, av0.w, av1.x, av1.y, av1.z, av1.w};
            #pragma unroll
            for (int i = 0; i < 8; i++) {
                u64 aa = pack2(av[i], av[i]);
                acc[i][0] = ffma2(aa, bb0, acc[i][0]);
                acc[i][1] = ffma2(aa, bb1, acc[i][1]);
                acc[i][2] = ffma2(aa, bb2, acc[i][2]);
                acc[i][3] = ffma2(aa, bb3, acc[i][3]);
            }
        }
        if (more) {
            float* Asb1 = As + (buf ^ 1) * 2048;
            float* Bsb1 = Bs + (buf ^ 1) * 2048;
            Asb1[(akc+0)*128 + arow] = ra0.x; Asb1[(akc+1)*128 + arow] = ra0.y;
            Asb1[(akc+2)*128 + arow] = ra0.z; Asb1[(akc+3)*128 + arow] = ra0.w;
            Asb1[(akc+0)*128 + arow+64] = ra1.x; Asb1[(akc+1)*128 + arow+64] = ra1.y;
            Asb1[(akc+2)*128 + arow+64] = ra1.z; Asb1[(akc+3)*128 + arow+64] = ra1.w;
            *(float4*)(Bsb1 + bk*128 + bc)     = rb0;
            *(float4*)(Bsb1 + bk*128 + bc + 4) = rb1;
        }
        __syncthreads();
        buf ^= 1;
    }

    float4 bba = *(const float4*)(bias + n0 + tc*4);
    float4 bbb = *(const float4*)(bias + n0 + 64 + tc*4);
    #pragma unroll
    for (int i = 0; i < 8; i++) {
        int gm = m0 + tr*8 + i;
        float x0,x1,x2,x3,y0,y1,y2,y3;
        unpack2(acc[i][0], x0, x1); unpack2(acc[i][1], x2, x3);
        unpack2(acc[i][2], y0, y1); unpack2(acc[i][3], y2, y3);
        float4 o0 = make_float4(x0+bba.x, x1+bba.y, x2+bba.z, x3+bba.w);
        float4 o1 = make_float4(y0+bbb.x, y1+bbb.y, y2+bbb.z, y3+bbb.w);
        *(float4*)(C + (size_t)gm*768 + n0 + tc*4)      = o0;
        *(float4*)(C + (size_t)gm*768 + n0 + 64 + tc*4) = o1;
    }
}

// ---------------- mega GEMM: utter (7500) + resp (300) + MT19937 (1) ----------------
__global__ __launch_bounds__(256) void mega_gemm_kernel(
    const float* __restrict__ emb_u, const float* __restrict__ emb_r,
    const int* __restrict__ toku, const int* __restrict__ tokr,
    const float* __restrict__ WTu_i, const float* __restrict__ ubih,
    const float* __restrict__ WTr_i, const float* __restrict__ rbih,
    float* __restrict__ GIu, float* __restrict__ GIr, float* __restrict__ tables)
{
    __shared__ float As[2*16*128];
    __shared__ float Bs[2*16*128];
    __shared__ unsigned mtA[624], mtB[624];
    int b = blockIdx.x;
    if (b < 7500) {
        int mb = b % 1250, nb = b / 1250;
        gemm_body(nullptr, toku, emb_u, WTu_i, ubih, GIu, mb*128, nb*128, 256, As, Bs);
    } else if (b < 7800) {
        int b2 = b - 7500;
        int mb = b2 % 50, nb = b2 / 50;
        gemm_body(nullptr, tokr, emb_r, WTr_i, rbih, GIr, mb*128, nb*128, 256, As, Bs);
    } else {
        mt_body(tables, mtA, mtB);
    }
}

__global__ __launch_bounds__(256) void gemm_ctx_kernel(
    const float* __restrict__ cin, const float* __restrict__ WTc_i,
    const float* __restrict__ cbih, float* __restrict__ GIc)
{
    __shared__ float As[2*16*128];
    __shared__ float Bs[2*16*128];
    int mb = blockIdx.x % 25, nb = blockIdx.x / 25;
    gemm_body(cin, nullptr, nullptr, WTc_i, cbih, GIc, mb*128, nb*128, 512, As, Bs);
}

// ---------------- GRU step with cp.async-staged W (double-buffered, BK=16) ----------------
#define PS_ 36
#define WS_TILE 12288           // 16*768 floats
#define SMEM_UR ((2*WS_TILE + 256*PS_) * 4)   // 135168 B

template<int ROWS>
__device__ __forceinline__ void gru_body2(
    const float* __restrict__ GI, float* __restrict__ h,
    const float* __restrict__ WT, const float* __restrict__ bhh,
    float* __restrict__ outp, int out_mode, int t, int row0,
    float* __restrict__ Ws, float* __restrict__ hs)
{
    const int tid = threadIdx.x;
    // load h tile: hs[k*PS_ + r]
    #pragma unroll
    for (int idx = tid; idx < ROWS*256; idx += 256) {
        int r = idx >> 8, k = idx & 255;
        hs[k*PS_ + r] = h[(size_t)(row0 + r)*256 + k];
    }
    // prefetch W tile 0
    for (int i = tid; i < 3072; i += 256)
        cp_async16(Ws + i*4, WT + i*4);
    cp_commit();

    u64 aR[ROWS/2], aZ[ROWS/2], aN[ROWS/2];
    #pragma unroll
    for (int p = 0; p < ROWS/2; p++) { aR[p]=0ull; aZ[p]=0ull; aN[p]=0ull; }

    for (int kt = 0; kt < 16; kt++) {
        const float* Wsb = Ws + (kt & 1) * WS_TILE;
        if (kt < 15) {
            float* Wn = Ws + ((kt + 1) & 1) * WS_TILE;
            const float* src = WT + (size_t)(kt + 1) * 16 * 768;
            for (int i = tid; i < 3072; i += 256)
                cp_async16(Wn + i*4, src + i*4);
            cp_commit();
            cp_wait<1>();
        } else {
            cp_wait<0>();
        }
        __syncthreads();
        #pragma unroll
        for (int kk = 0; kk < 16; kk++) {
            int k = kt*16 + kk;
            float w0 = Wsb[kk*768 + tid];
            float w1 = Wsb[kk*768 + 256 + tid];
            float w2 = Wsb[kk*768 + 512 + tid];
            u64 W0 = pack2(w0, w0), W1 = pack2(w1, w1), W2 = pack2(w2, w2);
            const ulonglong2* hp = (const ulonglong2*)(hs + k*PS_);
            #pragma unroll
            for (int p2 = 0; p2 < ROWS/4; p2++) {
                ulonglong2 hv2 = hp[p2];
                aR[2*p2]   = ffma2(hv2.x, W0, aR[2*p2]);
                aZ[2*p2]   = ffma2(hv2.x, W1, aZ[2*p2]);
                aN[2*p2]   = ffma2(hv2.x, W2, aN[2*p2]);
                aR[2*p2+1] = ffma2(hv2.y, W0, aR[2*p2+1]);
                aZ[2*p2+1] = ffma2(hv2.y, W1, aZ[2*p2+1]);
                aN[2*p2+1] = ffma2(hv2.y, W2, aN[2*p2+1]);
            }
        }
        __syncthreads();
    }
    const float br = bhh[tid], bz = bhh[tid+256], bn = bhh[tid+512];
    #pragma unroll
    for (int p = 0; p < ROWS/2; p++) {
        float aRl,aRh,aZl,aZh,aNl,aNh;
        unpack2(aR[p], aRl, aRh); unpack2(aZ[p], aZl, aZh); unpack2(aN[p], aNl, aNh);
        #pragma unroll
        for (int q = 0; q < 2; q++) {
            int r = 2*p + q;
            float accR = q ? aRh : aRl;
            float accZ = q ? aZh : aZl;
            float accN = q ? aNh : aNl;
            int grow = row0 + r;
            const float* gi = GI + (size_t)grow*768;
            float ir = gi[tid], iz = gi[tid+256], inn = gi[tid+512];
            float rg = 1.f / (1.f + expf(-(ir + accR + br)));
            float z  = 1.f / (1.f + expf(-(iz + accZ + bz)));
            float nn = tanhf(inn + rg * (accN + bn));
            float hold = hs[tid*PS_ + r];
            float hnew = (1.f - z) * nn + z * hold;
            h[(size_t)grow*256 + tid] = hnew;
            if (out_mode == 1) {
                outp[(size_t)grow*256 + tid] = hnew;
            } else if (out_mode == 2) {
                int rr = grow & 1, bb = grow >> 1;
                outp[(((size_t)rr*T_ + t)*B_ + bb)*256 + tid] = hnew;
            }
        }
    }
}

// utter (100 blocks x 32 rows) + resp (16 blocks x 8 rows)
__global__ __launch_bounds__(256) void step_ur_kernel(
    const float* __restrict__ GIu, const float* __restrict__ GIr,
    float* __restrict__ hu, float* __restrict__ hr,
    const float* __restrict__ WTu_h, const float* __restrict__ ubhh,
    const float* __restrict__ WTr_h, const float* __restrict__ rbhh,
    float* __restrict__ respout, int t)
{
    extern __shared__ float sm[];
    float* Ws = sm;
    float* hs = sm + 2*WS_TILE;
    if (blockIdx.x < 100)
        gru_body2<32>(GIu + (size_t)t*NU_*768, hu, WTu_h, ubhh, nullptr, 0, t, blockIdx.x*32, Ws, hs);
    else
        gru_body2<8>(GIr + (size_t)t*NR_*768, hr, WTr_h, rbhh, respout, 2, t, (blockIdx.x - 100)*8, Ws, hs);
}

// ---------------- ctx/speaker 3-stage pipeline, 1 row per block ----------------
// blocks 0-63: ctx GRU step i; 64-127: GIs rows for step i-1; 128-191: spk hidden step i-2
__global__ __launch_bounds__(256) void step_cs_kernel(
    const float* __restrict__ GIc, float* __restrict__ hc,
    const float* __restrict__ WTc_h, const float* __restrict__ cbhh,
    float* __restrict__ ctxout,
    float* __restrict__ GIs, const float* __restrict__ WTs_i, const float* __restrict__ sbih,
    float* __restrict__ hspk, const int* __restrict__ spk,
    const float* __restrict__ WTs_h, const float* __restrict__ sbhh, int i)
{
    __shared__ float sh[256];
    const int bx = blockIdx.x;
    const int j = threadIdx.x;
    if (bx < 64) {
        if (i >= S_) return;
        const int b = bx;
        sh[j] = hc[b*256 + j];
        __syncthreads();
        float aR = 0.f, aZ = 0.f, aN = 0.f;
        const float* W = WTc_h + j;
        #pragma unroll 8
        for (int k = 0; k < 256; k++) {
            float hv = sh[k];
            aR = fmaf(hv, __ldg(W + (size_t)k*768),       aR);
            aZ = fmaf(hv, __ldg(W + (size_t)k*768 + 256), aZ);
            aN = fmaf(hv, __ldg(W + (size_t)k*768 + 512), aN);
        }
        const float* gi = GIc + ((size_t)i*B_ + b)*768;
        float rg = 1.f / (1.f + expf(-(gi[j] + aR + cbhh[j])));
        float z  = 1.f / (1.f + expf(-(gi[j+256] + aZ + cbhh[j+256])));
        float nn = tanhf(gi[j+512] + rg * (aN + cbhh[j+512]));
        float hnew = (1.f - z) * nn + z * sh[j];
        hc[b*256 + j] = hnew;
        ctxout[((size_t)i*B_ + b)*256 + j] = hnew;
    } else if (bx < 128) {
        const int s = i - 1;
        if (s < 0 || s >= S_) return;
        const int b = bx - 64;
        sh[j] = ctxout[((size_t)s*B_ + b)*256 + j];
        __syncthreads();
        float aR = 0.f, aZ = 0.f, aN = 0.f;
        const float* W = WTs_i + j;
        #pragma unroll 8
        for (int k = 0; k < 256; k++) {
            float hv = sh[k];
            aR = fmaf(hv, __ldg(W + (size_t)k*768),       aR);
            aZ = fmaf(hv, __ldg(W + (size_t)k*768 + 256), aZ);
            aN = fmaf(hv, __ldg(W + (size_t)k*768 + 512), aN);
        }
        float* gis = GIs + ((size_t)s*B_ + b)*768;
        gis[j]     = aR + sbih[j];
        gis[j+256] = aZ + sbih[j+256];
        gis[j+512] = aN + sbih[j+512];
    } else {
        const int s = i - 2;
        if (s < 0 || s >= S_) return;
        const int b = bx - 128;
        const int id = spk[b*S_ + s];
        float* hrow = hspk + ((size_t)b*(S_+1) + id)*256;
        sh[j] = hrow[j];
        __syncthreads();
        float aR = 0.f, aZ = 0.f, aN = 0.f;
        const float* W = WTs_h + j;
        #pragma unroll 8
        for (int k = 0; k < 256; k++) {
            float hv = sh[k];
            aR = fmaf(hv, __ldg(W + (size_t)k*768),       aR);
            aZ = fmaf(hv, __ldg(W + (size_t)k*768 + 256), aZ);
            aN = fmaf(hv, __ldg(W + (size_t)k*768 + 512), aN);
        }
        const float* gis = GIs + ((size_t)s*B_ + b)*768;
        float rg = 1.f / (1.f + expf(-(gis[j] + aR + sbhh[j])));
        float z  = 1.f / (1.f + expf(-(gis[j+256] + aZ + sbhh[j+256])));
        float nn = tanhf(gis[j+512] + rg * (aN + sbhh[j+512]));
        hrow[j] = (1.f - z) * nn + z * sh[j];
    }
}

// ---------------- prep kernel ----------------
#define SEG_T256 196608
#define SEG_T512 393216
#define PREP_TOTAL (196608*7 + 393216 + 160000 + 6400 + 819200 + 16384 + 32768 + 835584 + 3264)

__global__ void prep_kernel(
    const int* __restrict__ context, const int* __restrict__ response, const int* __restrict__ spk,
    const float* __restrict__ uWih, const float* __restrict__ uWhh,
    const float* __restrict__ cWih, const float* __restrict__ cWhh,
    const float* __restrict__ rWih, const float* __restrict__ rWhh,
    const float* __restrict__ sWih, const float* __restrict__ sWhh,
    float* __restrict__ WTu_i, float* __restrict__ WTu_h,
    float* __restrict__ WTc_i, float* __restrict__ WTc_h,
    float* __restrict__ WTr_i, float* __restrict__ WTr_h,
    float* __restrict__ WTs_i, float* __restrict__ WTs_h,
    int* __restrict__ toku, int* __restrict__ tokr,
    float* __restrict__ hu, float* __restrict__ hc, float* __restrict__ hr,
    float* __restrict__ hspk, int* __restrict__ pres)
{
    long i = (long)blockIdx.x*256 + threadIdx.x;
    if (i >= PREP_TOTAL) return;
    if (i < SEG_T256) { int g = i >> 8, k = i & 255; WTu_i[k*768 + g] = uWih[i]; return; }
    i -= SEG_T256;
    if (i < SEG_T256) { int g = i >> 8, k = i & 255; WTu_h[k*768 + g] = uWhh[i]; return; }
    i -= SEG_T256;
    if (i < SEG_T512) { int g = (int)(i / 512), k = (int)(i % 512); WTc_i[k*768 + g] = cWih[i]; return; }
    i -= SEG_T512;
    if (i < SEG_T256) { int g = i >> 8, k = i & 255; WTc_h[k*768 + g] = cWhh[i]; return; }
    i -= SEG_T256;
    if (i < SEG_T256) { int g = i >> 8, k = i & 255; WTr_i[k*768 + g] = rWih[i]; return; }
    i -= SEG_T256;
    if (i < SEG_T256) { int g = i >> 8, k = i & 255; WTr_h[k*768 + g] = rWhh[i]; return; }
    i -= SEG_T256;
    if (i < SEG_T256) { int g = i >> 8, k = i & 255; WTs_i[k*768 + g] = sWih[i]; return; }
    i -= SEG_T256;
    if (i < SEG_T256) { int g = i >> 8, k = i & 255; WTs_h[k*768 + g] = sWhh[i]; return; }
    i -= SEG_T256;
    if (i < MU_) { int t = (int)(i / NU_), n = (int)(i % NU_); toku[i] = context[n*T_ + t]; return; }
    i -= MU_;
    if (i < MR_) { int t = (int)(i / NR_), n = (int)(i % NR_); tokr[i] = response[n*T_ + t]; return; }
    i -= MR_;
    if (i < NU_*H_) { hu[i] = 0.f; return; }
    i -= NU_*H_;
    if (i < B_*H_) { hc[i] = 0.f; return; }
    i -= B_*H_;
    if (i < NR_*H_) { hr[i] = 0.f; return; }
    i -= NR_*H_;
    if (i < B_*(S_+1)*H_) { hspk[i] = 0.f; return; }
    i -= B_*(S_+1)*H_;
    {
        int b = (int)(i / (S_+1)), a = (int)(i % (S_+1));
        int p = 0;
        for (int s = 0; s < S_; s++) p |= (spk[b*S_ + s] == a);
        pres[i] = p;
    }
}

// ---------------- ctx input gather ----------------
__global__ void ctx_in_kernel(const float* __restrict__ hu, const float* __restrict__ tab,
                              const int* __restrict__ spk, float* __restrict__ cin) {
    int i = blockIdx.x * blockDim.x + threadIdx.x;
    if (i < MC_ * 2 * H_) {
        int row = i / (2*H_), j = i % (2*H_);
        int s = row / B_, b = row % B_;
        float v;
        if (j < H_) v = hu[((size_t)b*S_ + s)*H_ + j];
        else        v = tab[((size_t)b*(S_+1) + spk[b*S_ + s])*H_ + (j - H_)];
        cin[i] = v;
    }
}

// ---------------- epilogue ----------------
#define EPI_TOTAL (16384 + 32768 + 835584)
__global__ void epilogue_kernel(float* __restrict__ out, const float* __restrict__ hr,
                                const float* __restrict__ hspk, const int* __restrict__ pres)
{
    long i = (long)blockIdx.x*256 + threadIdx.x;
    if (i >= EPI_TOTAL) return;
    if (i < 16384) { out[OFF_CTXHID + i] = out[OFF_CTXOUT + (size_t)(S_-1)*B_*H_ + i]; return; }
    i -= 16384;
    if (i < 32768) {
        int n = (int)(i >> 8), c = (int)(i & 255);
        int r = n % R_, b = n / R_;
        out[OFF_RESPHID + ((size_t)r*B_ + b)*H_ + c] = hr[i];
        return;
    }
    i -= 32768;
    {
        int ba = (int)(i >> 8);
        int p = pres[ba];
        out[OFF_SPKEMB + i] = p ? hspk[i] : 0.f;
        if ((i & 255) == 0) {
            int a = ba % (S_+1);
            out[OFF_MASK + ba] = (p && a > 0) ? 1.f : 0.f;
        }
    }
}

// ---------------- launch ----------------
extern "C" void kernel_launch(void* const* d_in, const int* in_sizes, int n_in,
                              void* d_out, int out_size)
{
    const int*   context  = (const int*)d_in[0];
    const int*   response = (const int*)d_in[1];
    const int*   spk      = (const int*)d_in[2];
    const float* emb_u    = (const float*)d_in[3];
    const float* emb_r    = (const float*)d_in[4];
    const float* uWih = (const float*)d_in[5];
    const float* uWhh = (const float*)d_in[6];
    const float* ubih = (const float*)d_in[7];
    const float* ubhh = (const float*)d_in[8];
    const float* cWih = (const float*)d_in[9];
    const float* cWhh = (const float*)d_in[10];
    const float* cbih = (const float*)d_in[11];
    const float* cbhh = (const float*)d_in[12];
    const float* rWih = (const float*)d_in[13];
    const float* rWhh = (const float*)d_in[14];
    const float* rbih = (const float*)d_in[15];
    const float* rbhh = (const float*)d_in[16];
    const float* sWih = (const float*)d_in[17];
    const float* sWhh = (const float*)d_in[18];
    const float* sbih = (const float*)d_in[19];
    const float* sbhh = (const float*)d_in[20];
    float* out = (float*)d_out;

    void *p;
    float *tab, *GIu, *GIc, *GIs, *GIr, *hu, *hc, *hr, *hspk, *cin;
    float *WTu_i, *WTu_h, *WTc_i, *WTc_h, *WTr_i, *WTr_h, *WTs_i, *WTs_h;
    int *toku, *tokr, *pres;
    cudaGetSymbolAddress(&p, g_tables); tab  = (float*)p;
    cudaGetSymbolAddress(&p, g_GIu);    GIu  = (float*)p;
    cudaGetSymbolAddress(&p, g_GIc);    GIc  = (float*)p;
    cudaGetSymbolAddress(&p, g_GIs);    GIs  = (float*)p;
    cudaGetSymbolAddress(&p, g_GIr);    GIr  = (float*)p;
    cudaGetSymbolAddress(&p, g_hu);     hu   = (float*)p;
    cudaGetSymbolAddress(&p, g_hc);     hc   = (float*)p;
    cudaGetSymbolAddress(&p, g_hr);     hr   = (float*)p;
    cudaGetSymbolAddress(&p, g_hspk);   hspk = (float*)p;
    cudaGetSymbolAddress(&p, g_ctxin);  cin  = (float*)p;
    cudaGetSymbolAddress(&p, g_WTu_i);  WTu_i = (float*)p;
    cudaGetSymbolAddress(&p, g_WTu_h);  WTu_h = (float*)p;
    cudaGetSymbolAddress(&p, g_WTc_i);  WTc_i = (float*)p;
    cudaGetSymbolAddress(&p, g_WTc_h);  WTc_h = (float*)p;
    cudaGetSymbolAddress(&p, g_WTr_i);  WTr_i = (float*)p;
    cudaGetSymbolAddress(&p, g_WTr_h);  WTr_h = (float*)p;
    cudaGetSymbolAddress(&p, g_WTs_i);  WTs_i = (float*)p;
    cudaGetSymbolAddress(&p, g_WTs_h);  WTs_h = (float*)p;
    cudaGetSymbolAddress(&p, g_toku);   toku = (int*)p;
    cudaGetSymbolAddress(&p, g_tokr);   tokr = (int*)p;
    cudaGetSymbolAddress(&p, g_present); pres = (int*)p;

    cudaFuncSetAttribute(step_ur_kernel, cudaFuncAttributeMaxDynamicSharedMemorySize, SMEM_UR);

    // 1. prep
    prep_kernel<<<(PREP_TOTAL + 255)/256, 256>>>(
        context, response, spk,
        uWih, uWhh, cWih, cWhh, rWih, rWhh, sWih, sWhh,
        WTu_i, WTu_h, WTc_i, WTc_h, WTr_i, WTr_h, WTs_i, WTs_h,
        toku, tokr, hu, hc, hr, hspk, pres);

    // 2. fused GEMMs + MT19937
    mega_gemm_kernel<<<7801, 256>>>(emb_u, emb_r, toku, tokr,
                                    WTu_i, ubih, WTr_i, rbih, GIu, GIr, tab);

    // 3. utterance + response recurrences (cp.async-staged W)
    for (int t = 0; t < T_; t++)
        step_ur_kernel<<<116, 256, SMEM_UR>>>(GIu, GIr, hu, hr, WTu_h, ubhh, WTr_h, rbhh,
                                              out + OFF_RESPOUT, t);

    // 4. context input + GEMM
    ctx_in_kernel<<<(MC_*2*H_ + 255)/256, 256>>>(hu, tab, spk, cin);
    gemm_ctx_kernel<<<150, 256>>>(cin, WTc_i, cbih, GIc);

    // 5. 3-stage pipelined ctx + GIs + speaker chain
    for (int i = 0; i <= S_ + 1; i++)
        step_cs_kernel<<<192, 256>>>(GIc, hc, WTc_h, cbhh, out + OFF_CTXOUT,
                                     GIs, WTs_i, sbih, hspk, spk, WTs_h, sbhh, i);

    // 6. epilogue
    epilogue_kernel<<<(EPI_TOTAL + 255)/256, 256>>>(out, hr, hspk, pres);
}

// round 4
// speedup vs baseline: 1.1538x; 1.1538x over previous
#include <cuda_runtime.h>
#include <cuda_bf16.h>
#include <math.h>

typedef unsigned long long u64;
typedef unsigned int u32;

// ---------------- constants ----------------
#define B_  64
#define S_  50
#define T_  50
#define R_  2
#define H_  256
#define NU_ (B_*S_)          // 3200
#define NR_ (B_*R_)          // 128
#define NALL_ (NU_+NR_)      // 3328
#define MU_ (T_*NU_)         // 160000
#define MR_ (T_*NR_)         // 6400
#define MC_ (S_*B_)          // 3200
#define TAB_N (B_*(S_+1)*H_) // 835584

// output offsets (f32 elements)
#define OFF_CTXOUT   0
#define OFF_CTXHID   819200
#define OFF_RESPOUT  835584
#define OFF_RESPHID  2473984
#define OFF_SPKEMB   2506752
#define OFF_MASK     3342336

// ---------------- static device scratch ----------------
__device__ float g_tables[TAB_N];
__device__ float g_GIu[(size_t)MU_*768];
__device__ float g_GIc[(size_t)MC_*768];
__device__ float g_GIr[(size_t)MR_*768];
__device__ float g_hall[NALL_*H_];                 // utter rows 0..3199, resp rows 3200..3327
__device__ __nv_bfloat16 g_hbf_hi[NALL_*H_];
__device__ __nv_bfloat16 g_hbf_lo[NALL_*H_];
__device__ float g_hc[B_*H_];
__device__ float g_hspk[B_*(S_+1)*H_];
__device__ float g_ctxin[MC_*2*H_];
__device__ float g_WTu_i[H_*768];
__device__ float g_WTc_i[2*H_*768], g_WTc_h[H_*768];
__device__ float g_WTr_i[H_*768];
__device__ float g_WTs_i[H_*768],  g_WTs_h[H_*768];
__device__ __nv_bfloat16 g_Wubf_hi[768*H_], g_Wubf_lo[768*H_];   // native [768,256] layout
__device__ __nv_bfloat16 g_Wrbf_hi[768*H_], g_Wrbf_lo[768*H_];
__device__ int   g_toku[MU_];
__device__ int   g_tokr[MR_];
__device__ int   g_present[B_*(S_+1)];

// ---------------- f32x2 helpers ----------------
__device__ __forceinline__ u64 pack2(float lo, float hi) {
    u64 r; asm("mov.b64 %0, {%1,%2};" : "=l"(r) : "f"(lo), "f"(hi)); return r;
}
__device__ __forceinline__ void unpack2(u64 a, float& lo, float& hi) {
    asm("mov.b64 {%0,%1}, %2;" : "=f"(lo), "=f"(hi) : "l"(a));
}
__device__ __forceinline__ u64 ffma2(u64 a, u64 b, u64 c) {
    u64 d; asm("fma.rn.f32x2 %0, %1, %2, %3;" : "=l"(d) : "l"(a), "l"(b), "l"(c)); return d;
}

// ---------------- MT19937 (NumPy-exact), 256-thread body ----------------
__device__ __forceinline__ unsigned mt_twist_fn(unsigned u, unsigned v) {
    unsigned y = (u & 0x80000000u) | (v & 0x7fffffffu);
    return (y >> 1) ^ ((v & 1u) ? 0x9908b0dfu : 0u);
}
__device__ __forceinline__ unsigned mt_temper(unsigned y) {
    y ^= y >> 11; y ^= (y << 7) & 0x9d2c5680u; y ^= (y << 15) & 0xefc60000u; y ^= y >> 18;
    return y;
}
__device__ void mt_body(float* __restrict__ tables, unsigned* bufA, unsigned* bufB) {
    const int tid = threadIdx.x;
    if (tid == 0) {
        unsigned s = 1u; bufA[0] = s;
        for (int i = 1; i < 624; i++) { s = 1812433253u * (s ^ (s >> 30)) + (unsigned)i; bufA[i] = s; }
    }
    __syncthreads();
    unsigned* cur = bufA; unsigned* nxt = bufB;
    const int NTW = (2*TAB_N + 623) / 624;   // 2679
    for (int tw = 0; tw < NTW; tw++) {
        if (tid < 227) nxt[tid] = cur[tid + 397] ^ mt_twist_fn(cur[tid], cur[tid + 1]);
        __syncthreads();
        if (tid < 227) { int i = 227 + tid; nxt[i] = nxt[i - 227] ^ mt_twist_fn(cur[i], cur[i + 1]); }
        __syncthreads();
        if (tid < 170) {
            int i = 454 + tid;
            unsigned v = (i == 623) ? nxt[0] : cur[i + 1];
            nxt[i] = nxt[i - 227] ^ mt_twist_fn(cur[i], v);
        }
        __syncthreads();
        for (int o = tid; o < 312; o += 256) {
            int outIdx = tw * 312 + o;
            if (outIdx < TAB_N) {
                unsigned a  = mt_temper(nxt[2*o])   >> 5;
                unsigned bv = mt_temper(nxt[2*o+1]) >> 6;
                tables[outIdx] = (float)(((double)a * 67108864.0 + (double)bv) * (1.0 / 9007199254740992.0));
            }
        }
        __syncthreads();
        unsigned* t2 = cur; cur = nxt; nxt = t2;
    }
}

// ---------------- fp32 GEMM body (R2): BM=BN=128, BK=16, 8x8/thread, FFMA2 ----------------
__device__ __forceinline__ void gemm_body(
    const float* __restrict__ A, const int* __restrict__ toks, const float* __restrict__ emb,
    const float* __restrict__ BT, const float* __restrict__ bias, float* __restrict__ C,
    int m0, int n0, int K, float* As, float* Bs)
{
    const int tid  = threadIdx.x;
    const int arow = tid >> 2;
    const int akc  = (tid & 3) << 2;
    const int bk   = tid >> 4;
    const int bc   = (tid & 15) << 3;
    const int tr   = tid >> 4;
    const int tc   = tid & 15;

    const float* arp0;
    const float* arp1;
    {
        int gm0 = m0 + arow, gm1 = m0 + arow + 64;
        arp0 = toks ? (emb + (size_t)__ldg(toks + gm0) * K) : (A + (size_t)gm0 * K);
        arp1 = toks ? (emb + (size_t)__ldg(toks + gm1) * K) : (A + (size_t)gm1 * K);
    }
    float4 ra0 = *(const float4*)(arp0 + akc);
    float4 ra1 = *(const float4*)(arp1 + akc);
    float4 rb0 = *(const float4*)(BT + (size_t)bk * 768 + n0 + bc);
    float4 rb1 = *(const float4*)(BT + (size_t)bk * 768 + n0 + bc + 4);
    {
        As[(akc+0)*128 + arow] = ra0.x; As[(akc+1)*128 + arow] = ra0.y;
        As[(akc+2)*128 + arow] = ra0.z; As[(akc+3)*128 + arow] = ra0.w;
        As[(akc+0)*128 + arow+64] = ra1.x; As[(akc+1)*128 + arow+64] = ra1.y;
        As[(akc+2)*128 + arow+64] = ra1.z; As[(akc+3)*128 + arow+64] = ra1.w;
        *(float4*)(Bs + bk*128 + bc)     = rb0;
        *(float4*)(Bs + bk*128 + bc + 4) = rb1;
    }
    __syncthreads();

    u64 acc[8][4];
    #pragma unroll
    for (int i = 0; i < 8; i++)
        #pragma unroll
        for (int j = 0; j < 4; j++) acc[i][j] = 0ull;

    int buf = 0;
    for (int k0 = 16; k0 <= K; k0 += 16) {
        const bool more = (k0 < K);
        if (more) {
            ra0 = *(const float4*)(arp0 + k0 + akc);
            ra1 = *(const float4*)(arp1 + k0 + akc);
            rb0 = *(const float4*)(BT + (size_t)(k0 + bk) * 768 + n0 + bc);
            rb1 = *(const float4*)(BT + (size_t)(k0 + bk) * 768 + n0 + bc + 4);
        }
        const float* Asb = As + buf * 2048;
        const float* Bsb = Bs + buf * 2048;
        #pragma unroll
        for (int kk = 0; kk < 16; kk++) {
            float4 av0 = *(const float4*)(Asb + kk*128 + tr*8);
            float4 av1 = *(const float4*)(Asb + kk*128 + tr*8 + 4);
            u64 bb0 = *(const u64*)(Bsb + kk*128 + tc*4);
            u64 bb1 = *(const u64*)(Bsb + kk*128 + tc*4 + 2);
            u64 bb2 = *(const u64*)(Bsb + kk*128 + 64 + tc*4);
            u64 bb3 = *(const u64*)(Bsb + kk*128 + 64 + tc*4 + 2);
            float av[8] = {av0.x, av0.y, av0.z, av0.w, av1.x, av1.y, av1.z, av1.w};
            #pragma unroll
            for (int i = 0; i < 8; i++) {
                u64 aa = pack2(av[i], av[i]);
                acc[i][0] = ffma2(aa, bb0, acc[i][0]);
                acc[i][1] = ffma2(aa, bb1, acc[i][1]);
                acc[i][2] = ffma2(aa, bb2, acc[i][2]);
                acc[i][3] = ffma2(aa, bb3, acc[i][3]);
            }
        }
        if (more) {
            float* Asb1 = As + (buf ^ 1) * 2048;
            float* Bsb1 = Bs + (buf ^ 1) * 2048;
            Asb1[(akc+0)*128 + arow] = ra0.x; Asb1[(akc+1)*128 + arow] = ra0.y;
            Asb1[(akc+2)*128 + arow] = ra0.z; Asb1[(akc+3)*128 + arow] = ra0.w;
            Asb1[(akc+0)*128 + arow+64] = ra1.x; Asb1[(akc+1)*128 + arow+64] = ra1.y;
            Asb1[(akc+2)*128 + arow+64] = ra1.z; Asb1[(akc+3)*128 + arow+64] = ra1.w;
            *(float4*)(Bsb1 + bk*128 + bc)     = rb0;
            *(float4*)(Bsb1 + bk*128 + bc + 4) = rb1;
        }
        __syncthreads();
        buf ^= 1;
    }

    float4 bba = *(const float4*)(bias + n0 + tc*4);
    float4 bbb = *(const float4*)(bias + n0 + 64 + tc*4);
    #pragma unroll
    for (int i = 0; i < 8; i++) {
        int gm = m0 + tr*8 + i;
        float x0,x1,x2,x3,y0,y1,y2,y3;
        unpack2(acc[i][0], x0, x1); unpack2(acc[i][1], x2, x3);
        unpack2(acc[i][2], y0, y1); unpack2(acc[i][3], y2, y3);
        float4 o0 = make_float4(x0+bba.x, x1+bba.y, x2+bba.z, x3+bba.w);
        float4 o1 = make_float4(y0+bbb.x, y1+bbb.y, y2+bbb.z, y3+bbb.w);
        *(float4*)(C + (size_t)gm*768 + n0 + tc*4)      = o0;
        *(float4*)(C + (size_t)gm*768 + n0 + 64 + tc*4) = o1;
    }
}

// ---------------- mega GEMM: utter (7500) + resp (300) + MT19937 (1) ----------------
__global__ __launch_bounds__(256) void mega_gemm_kernel(
    const float* __restrict__ emb_u, const float* __restrict__ emb_r,
    const int* __restrict__ toku, const int* __restrict__ tokr,
    const float* __restrict__ WTu_i, const float* __restrict__ ubih,
    const float* __restrict__ WTr_i, const float* __restrict__ rbih,
    float* __restrict__ GIu, float* __restrict__ GIr, float* __restrict__ tables)
{
    __shared__ float As[2*16*128];
    __shared__ float Bs[2*16*128];
    __shared__ unsigned mtA[624], mtB[624];
    int b = blockIdx.x;
    if (b < 7500) {
        int mb = b % 1250, nb = b / 1250;
        gemm_body(nullptr, toku, emb_u, WTu_i, ubih, GIu, mb*128, nb*128, 256, As, Bs);
    } else if (b < 7800) {
        int b2 = b - 7500;
        int mb = b2 % 50, nb = b2 / 50;
        gemm_body(nullptr, tokr, emb_r, WTr_i, rbih, GIr, mb*128, nb*128, 256, As, Bs);
    } else {
        mt_body(tables, mtA, mtB);
    }
}

__global__ __launch_bounds__(256) void gemm_ctx_kernel(
    const float* __restrict__ cin, const float* __restrict__ WTc_i,
    const float* __restrict__ cbih, float* __restrict__ GIc)
{
    __shared__ float As[2*16*128];
    __shared__ float Bs[2*16*128];
    int mb = blockIdx.x % 25, nb = blockIdx.x / 25;
    gemm_body(cin, nullptr, nullptr, WTc_i, cbih, GIc, mb*128, nb*128, 512, As, Bs);
}

// ---------------- mma.sync bf16 split-precision GRU step ----------------
// grid 208: blocks 0..199 = utter (16 rows each), 200..207 = resp (16 rows each)
// per block: C[16,768] = h[16,256] @ W^T via 3 passes (hi*Whi + lo*Whi + hi*Wlo)
#define CS_PITCH 776
#define SMEM_STEP (16*CS_PITCH*4)   // 49664 B

__device__ __forceinline__ void mma_bf16(float* c, const u32* a, u32 b0, u32 b1) {
    asm volatile(
        "mma.sync.aligned.m16n8k16.row.col.f32.bf16.bf16.f32 "
        "{%0,%1,%2,%3}, {%4,%5,%6,%7}, {%8,%9}, {%0,%1,%2,%3};"
        : "+f"(c[0]), "+f"(c[1]), "+f"(c[2]), "+f"(c[3])
        : "r"(a[0]), "r"(a[1]), "r"(a[2]), "r"(a[3]), "r"(b0), "r"(b1));
}

__global__ __launch_bounds__(256, 2) void step_mma_kernel(
    const float* __restrict__ GIu, const float* __restrict__ GIr,
    float* __restrict__ hall,
    __nv_bfloat16* __restrict__ h_hi, __nv_bfloat16* __restrict__ h_lo,
    const __nv_bfloat16* __restrict__ Wu_hi, const __nv_bfloat16* __restrict__ Wu_lo,
    const __nv_bfloat16* __restrict__ Wr_hi, const __nv_bfloat16* __restrict__ Wr_lo,
    const float* __restrict__ ubhh, const float* __restrict__ rbhh,
    float* __restrict__ respout, int t)
{
    extern __shared__ float Cs[];   // [16][CS_PITCH]
    const int bx = blockIdx.x;
    const bool isResp = bx >= 200;
    const int row0 = isResp ? NU_ + (bx - 200)*16 : bx*16;
    const __nv_bfloat16* Whi = isResp ? Wr_hi : Wu_hi;
    const __nv_bfloat16* Wlo = isResp ? Wr_lo : Wu_lo;
    const float* bhh = isResp ? rbhh : ubhh;
    const float* GI = isResp ? (GIr + (size_t)t*NR_*768 + (size_t)(bx - 200)*16*768)
                             : (GIu + (size_t)t*NU_*768 + (size_t)bx*16*768);

    const int tid = threadIdx.x;
    const int wid = tid >> 5, lane = tid & 31;
    const int g = lane >> 2, tg = lane & 3;
    const int n0 = wid * 96;

    float acc[12][4];
    #pragma unroll
    for (int nt = 0; nt < 12; nt++)
        #pragma unroll
        for (int i = 0; i < 4; i++) acc[nt][i] = 0.f;

    #pragma unroll 1
    for (int pass = 0; pass < 3; pass++) {
        const __nv_bfloat16* Ab = (pass == 1) ? h_lo : h_hi;
        const __nv_bfloat16* Bb = (pass == 2) ? Wlo : Whi;
        #pragma unroll 2
        for (int kt = 0; kt < 16; kt++) {
            const int k0 = kt*16;
            u32 a[4];
            const __nv_bfloat16* ap = Ab + (size_t)(row0 + g)*256 + k0 + tg*2;
            a[0] = *(const u32*)ap;
            a[1] = *(const u32*)(ap + 8*256);
            a[2] = *(const u32*)(ap + 8);
            a[3] = *(const u32*)(ap + 8*256 + 8);
            #pragma unroll
            for (int nt = 0; nt < 12; nt++) {
                const __nv_bfloat16* bp = Bb + (size_t)(n0 + nt*8 + g)*256 + k0 + tg*2;
                u32 b0 = *(const u32*)bp;
                u32 b1 = *(const u32*)(bp + 8);
                mma_bf16(acc[nt], a, b0, b1);
            }
        }
    }

    // store C fragments to smem
    #pragma unroll
    for (int nt = 0; nt < 12; nt++) {
        int c = n0 + nt*8 + tg*2;
        Cs[g*CS_PITCH + c]       = acc[nt][0];
        Cs[g*CS_PITCH + c + 1]   = acc[nt][1];
        Cs[(g+8)*CS_PITCH + c]     = acc[nt][2];
        Cs[(g+8)*CS_PITCH + c + 1] = acc[nt][3];
    }
    __syncthreads();

    // gate epilogue: thread j = tid, 16 rows
    const float br = bhh[tid], bz = bhh[tid+256], bn = bhh[tid+512];
    #pragma unroll 4
    for (int r = 0; r < 16; r++) {
        const int grow = row0 + r;
        const float* gi = GI + (size_t)r*768;
        float aR = Cs[r*CS_PITCH + tid];
        float aZ = Cs[r*CS_PITCH + tid + 256];
        float aN = Cs[r*CS_PITCH + tid + 512];
        float ir = gi[tid], iz = gi[tid+256], inn = gi[tid+512];
        float rg = 1.f / (1.f + expf(-(ir + aR + br)));
        float z  = 1.f / (1.f + expf(-(iz + aZ + bz)));
        float nn = tanhf(inn + rg * (aN + bn));
        float hold = hall[(size_t)grow*256 + tid];
        float hnew = (1.f - z) * nn + z * hold;
        hall[(size_t)grow*256 + tid] = hnew;
        __nv_bfloat16 hi = __float2bfloat16(hnew);
        h_hi[(size_t)grow*256 + tid] = hi;
        h_lo[(size_t)grow*256 + tid] = __float2bfloat16(hnew - __bfloat162float(hi));
        if (isResp) {
            int n = grow - NU_;
            int rr = n & 1, bb = n >> 1;
            respout[(((size_t)rr*T_ + t)*B_ + bb)*256 + tid] = hnew;
        }
    }
}

// ---------------- R2-style small GRU body (for ctx chain) ----------------
template<int ROWS>
__device__ __forceinline__ void gru_body(
    const float* __restrict__ GI, float* __restrict__ h,
    const float* __restrict__ WT, const float* __restrict__ bhh,
    float* __restrict__ outp, int out_mode, int t, int row0, float* hs)
{
    constexpr int PS = ROWS + 2;
    const int tid = threadIdx.x;
    for (int idx = tid; idx < ROWS*256; idx += 256) {
        int r = idx >> 8, k = idx & 255;
        hs[k*PS + r] = h[(size_t)(row0 + r)*256 + k];
    }
    __syncthreads();
    u64 aR[ROWS/2], aZ[ROWS/2], aN[ROWS/2];
    #pragma unroll
    for (int p = 0; p < ROWS/2; p++) { aR[p]=0ull; aZ[p]=0ull; aN[p]=0ull; }
    const float* Wp = WT + tid;
    #pragma unroll 4
    for (int k = 0; k < 256; k++) {
        float w0 = __ldg(Wp + (size_t)k*768);
        float w1 = __ldg(Wp + (size_t)k*768 + 256);
        float w2 = __ldg(Wp + (size_t)k*768 + 512);
        u64 W0 = pack2(w0, w0), W1 = pack2(w1, w1), W2 = pack2(w2, w2);
        const u64* hp = (const u64*)(hs + k*PS);
        #pragma unroll
        for (int p = 0; p < ROWS/2; p++) {
            u64 hv = hp[p];
            aR[p] = ffma2(hv, W0, aR[p]);
            aZ[p] = ffma2(hv, W1, aZ[p]);
            aN[p] = ffma2(hv, W2, aN[p]);
        }
    }
    const float br = bhh[tid], bz = bhh[tid+256], bn = bhh[tid+512];
    #pragma unroll
    for (int p = 0; p < ROWS/2; p++) {
        float aRl,aRh,aZl,aZh,aNl,aNh;
        unpack2(aR[p], aRl, aRh); unpack2(aZ[p], aZl, aZh); unpack2(aN[p], aNl, aNh);
        #pragma unroll
        for (int q = 0; q < 2; q++) {
            int r = 2*p + q;
            float accR = q ? aRh : aRl;
            float accZ = q ? aZh : aZl;
            float accN = q ? aNh : aNl;
            int grow = row0 + r;
            const float* gi = GI + (size_t)grow*768;
            float ir = gi[tid], iz = gi[tid+256], inn = gi[tid+512];
            float rg = 1.f / (1.f + expf(-(ir + accR + br)));
            float z  = 1.f / (1.f + expf(-(iz + accZ + bz)));
            float nn = tanhf(inn + rg * (accN + bn));
            float hold = hs[tid*PS + r];
            float hnew = (1.f - z) * nn + z * hold;
            h[(size_t)grow*256 + tid] = hnew;
            if (out_mode == 1) outp[(size_t)grow*256 + tid] = hnew;
        }
    }
}

// ---------------- speaker step body (R2): only active row per batch updates ----------------
__device__ void spk_body(const float* __restrict__ ctxout_s,
                         float* __restrict__ hspk, const int* __restrict__ spk,
                         const float* __restrict__ WTi, const float* __restrict__ WTh,
                         const float* __restrict__ bih, const float* __restrict__ bhh,
                         int s, int b0, float* sm)
{
    const int tid = threadIdx.x;
    float* cs  = sm;             // [k*6 + r]
    float* hsv = sm + 256*6;     // [k*6 + r]
    int id[4];
    #pragma unroll
    for (int r = 0; r < 4; r++) id[r] = spk[(b0 + r)*S_ + s];
    for (int idx = tid; idx < 4*256; idx += 256) {
        int r = idx >> 8, k = idx & 255;
        cs[k*6 + r]  = ctxout_s[(size_t)(b0 + r)*256 + k];
        hsv[k*6 + r] = hspk[((size_t)(b0 + r)*(S_+1) + id[r])*256 + k];
    }
    __syncthreads();
    u64 iR[2]={0ull,0ull}, iZ[2]={0ull,0ull}, iN[2]={0ull,0ull};
    u64 hR[2]={0ull,0ull}, hZ[2]={0ull,0ull}, hN[2]={0ull,0ull};
    #pragma unroll 2
    for (int k = 0; k < 256; k++) {
        float wi0 = __ldg(WTi + (size_t)k*768 + tid);
        float wi1 = __ldg(WTi + (size_t)k*768 + 256 + tid);
        float wi2 = __ldg(WTi + (size_t)k*768 + 512 + tid);
        float wh0 = __ldg(WTh + (size_t)k*768 + tid);
        float wh1 = __ldg(WTh + (size_t)k*768 + 256 + tid);
        float wh2 = __ldg(WTh + (size_t)k*768 + 512 + tid);
        u64 Wi0 = pack2(wi0,wi0), Wi1 = pack2(wi1,wi1), Wi2 = pack2(wi2,wi2);
        u64 Wh0 = pack2(wh0,wh0), Wh1 = pack2(wh1,wh1), Wh2 = pack2(wh2,wh2);
        const u64* cp = (const u64*)(cs + k*6);
        const u64* hp = (const u64*)(hsv + k*6);
        #pragma unroll
        for (int p = 0; p < 2; p++) {
            u64 cv = cp[p], hv = hp[p];
            iR[p] = ffma2(cv, Wi0, iR[p]); iZ[p] = ffma2(cv, Wi1, iZ[p]); iN[p] = ffma2(cv, Wi2, iN[p]);
            hR[p] = ffma2(hv, Wh0, hR[p]); hZ[p] = ffma2(hv, Wh1, hZ[p]); hN[p] = ffma2(hv, Wh2, hN[p]);
        }
    }
    const float bi0 = bih[tid], bi1 = bih[tid+256], bi2 = bih[tid+512];
    const float bh0 = bhh[tid], bh1 = bhh[tid+256], bh2 = bhh[tid+512];
    #pragma unroll
    for (int p = 0; p < 2; p++) {
        float iRl,iRh,iZl,iZh,iNl,iNh,hRl,hRh,hZl,hZh,hNl,hNh;
        unpack2(iR[p],iRl,iRh); unpack2(iZ[p],iZl,iZh); unpack2(iN[p],iNl,iNh);
        unpack2(hR[p],hRl,hRh); unpack2(hZ[p],hZl,hZh); unpack2(hN[p],hNl,hNh);
        #pragma unroll
        for (int q = 0; q < 2; q++) {
            int r = 2*p + q;
            float giR = (q ? iRh : iRl) + bi0;
            float giZ = (q ? iZh : iZl) + bi1;
            float giN = (q ? iNh : iNl) + bi2;
            float ghR = (q ? hRh : hRl) + bh0;
            float ghZ = (q ? hZh : hZl) + bh1;
            float ghN = (q ? hNh : hNl) + bh2;
            float rg = 1.f / (1.f + expf(-(giR + ghR)));
            float z  = 1.f / (1.f + expf(-(giZ + ghZ)));
            float nn = tanhf(giN + rg * ghN);
            float hold = hsv[tid*6 + r];
            float hnew = (1.f - z) * nn + z * hold;
            hspk[((size_t)(b0 + r)*(S_+1) + id[r])*256 + tid] = hnew;
        }
    }
}

// ctx step i (16 blocks x 4 rows) + spk step i-1 (16 blocks x 4 batches)
__global__ __launch_bounds__(256) void step_cs_kernel(
    const float* __restrict__ GIc, float* __restrict__ hc,
    const float* __restrict__ WTc_h, const float* __restrict__ cbhh,
    float* __restrict__ ctxout, float* __restrict__ hspk, const int* __restrict__ spk,
    const float* __restrict__ WTs_i, const float* __restrict__ WTs_h,
    const float* __restrict__ sbih, const float* __restrict__ sbhh, int i)
{
    __shared__ float sm[256*12];
    if (blockIdx.x < 16) {
        if (i < S_)
            gru_body<4>(GIc + (size_t)i*B_*768, hc, WTc_h, cbhh,
                        ctxout + (size_t)i*B_*256, 1, i, blockIdx.x*4, sm);
    } else {
        int s = i - 1;
        if (s >= 0)
            spk_body(ctxout + (size_t)s*B_*256, hspk, spk, WTs_i, WTs_h, sbih, sbhh,
                     s, (blockIdx.x - 16)*4, sm);
    }
}

// ---------------- prep kernel ----------------
#define SEG_T256 196608
#define SEG_T512 393216
#define PREP_TOTAL (196608*5 + 393216 + 196608*2 + 160000 + 6400 + 851968 + 16384 + 835584 + 3264)

__global__ void prep_kernel(
    const int* __restrict__ context, const int* __restrict__ response, const int* __restrict__ spk,
    const float* __restrict__ uWih, const float* __restrict__ uWhh,
    const float* __restrict__ cWih, const float* __restrict__ cWhh,
    const float* __restrict__ rWih, const float* __restrict__ rWhh,
    const float* __restrict__ sWih, const float* __restrict__ sWhh,
    float* __restrict__ WTu_i,
    float* __restrict__ WTc_i, float* __restrict__ WTc_h,
    float* __restrict__ WTr_i,
    float* __restrict__ WTs_i, float* __restrict__ WTs_h,
    __nv_bfloat16* __restrict__ Wu_hi, __nv_bfloat16* __restrict__ Wu_lo,
    __nv_bfloat16* __restrict__ Wr_hi, __nv_bfloat16* __restrict__ Wr_lo,
    int* __restrict__ toku, int* __restrict__ tokr,
    float* __restrict__ hall, __nv_bfloat16* __restrict__ h_hi, __nv_bfloat16* __restrict__ h_lo,
    float* __restrict__ hc, float* __restrict__ hspk, int* __restrict__ pres)
{
    long i = (long)blockIdx.x*256 + threadIdx.x;
    if (i >= PREP_TOTAL) return;
    if (i < SEG_T256) { int g = i >> 8, k = i & 255; WTu_i[k*768 + g] = uWih[i]; return; }
    i -= SEG_T256;
    if (i < SEG_T512) { int g = (int)(i / 512), k = (int)(i % 512); WTc_i[k*768 + g] = cWih[i]; return; }
    i -= SEG_T512;
    if (i < SEG_T256) { int g = i >> 8, k = i & 255; WTc_h[k*768 + g] = cWhh[i]; return; }
    i -= SEG_T256;
    if (i < SEG_T256) { int g = i >> 8, k = i & 255; WTr_i[k*768 + g] = rWih[i]; return; }
    i -= SEG_T256;
    if (i < SEG_T256) { int g = i >> 8, k = i & 255; WTs_i[k*768 + g] = sWih[i]; return; }
    i -= SEG_T256;
    if (i < SEG_T256) { int g = i >> 8, k = i & 255; WTs_h[k*768 + g] = sWhh[i]; return; }
    i -= SEG_T256;
    if (i < SEG_T256) {   // utter Whh -> bf16 hi/lo (native layout)
        float w = uWhh[i];
        __nv_bfloat16 hi = __float2bfloat16(w);
        Wu_hi[i] = hi;
        Wu_lo[i] = __float2bfloat16(w - __bfloat162float(hi));
        return;
    }
    i -= SEG_T256;
    if (i < SEG_T256) {   // resp Whh -> bf16 hi/lo
        float w = rWhh[i];
        __nv_bfloat16 hi = __float2bfloat16(w);
        Wr_hi[i] = hi;
        Wr_lo[i] = __float2bfloat16(w - __bfloat162float(hi));
        return;
    }
    i -= SEG_T256;
    if (i < MU_) { int t = (int)(i / NU_), n = (int)(i % NU_); toku[i] = context[n*T_ + t]; return; }
    i -= MU_;
    if (i < MR_) { int t = (int)(i / NR_), n = (int)(i % NR_); tokr[i] = response[n*T_ + t]; return; }
    i -= MR_;
    if (i < NALL_*H_) { hall[i] = 0.f; h_hi[i] = __float2bfloat16(0.f); h_lo[i] = __float2bfloat16(0.f); return; }
    i -= NALL_*H_;
    if (i < B_*H_) { hc[i] = 0.f; return; }
    i -= B_*H_;
    if (i < B_*(S_+1)*H_) { hspk[i] = 0.f; return; }
    i -= B_*(S_+1)*H_;
    {
        int b = (int)(i / (S_+1)), a = (int)(i % (S_+1));
        int p = 0;
        for (int s = 0; s < S_; s++) p |= (spk[b*S_ + s] == a);
        pres[i] = p;
    }
}

// ---------------- ctx input gather ----------------
__global__ void ctx_in_kernel(const float* __restrict__ hall, const float* __restrict__ tab,
                              const int* __restrict__ spk, float* __restrict__ cin) {
    int i = blockIdx.x * blockDim.x + threadIdx.x;
    if (i < MC_ * 2 * H_) {
        int row = i / (2*H_), j = i % (2*H_);
        int s = row / B_, b = row % B_;
        float v;
        if (j < H_) v = hall[((size_t)b*S_ + s)*H_ + j];
        else        v = tab[((size_t)b*(S_+1) + spk[b*S_ + s])*H_ + (j - H_)];
        cin[i] = v;
    }
}

// ---------------- epilogue ----------------
#define EPI_TOTAL (16384 + 32768 + 835584)
__global__ void epilogue_kernel(float* __restrict__ out, const float* __restrict__ hall,
                                const float* __restrict__ hspk, const int* __restrict__ pres)
{
    long i = (long)blockIdx.x*256 + threadIdx.x;
    if (i >= EPI_TOTAL) return;
    if (i < 16384) { out[OFF_CTXHID + i] = out[OFF_CTXOUT + (size_t)(S_-1)*B_*H_ + i]; return; }
    i -= 16384;
    if (i < 32768) {
        int n = (int)(i >> 8), c = (int)(i & 255);
        int r = n % R_, b = n / R_;
        out[OFF_RESPHID + ((size_t)r*B_ + b)*H_ + c] = hall[(size_t)(NU_ + n)*H_ + c];
        return;
    }
    i -= 32768;
    {
        int ba = (int)(i >> 8);
        int p = pres[ba];
        out[OFF_SPKEMB + i] = p ? hspk[i] : 0.f;
        if ((i & 255) == 0) {
            int a = ba % (S_+1);
            out[OFF_MASK + ba] = (p && a > 0) ? 1.f : 0.f;
        }
    }
}

// ---------------- launch ----------------
extern "C" void kernel_launch(void* const* d_in, const int* in_sizes, int n_in,
                              void* d_out, int out_size)
{
    const int*   context  = (const int*)d_in[0];
    const int*   response = (const int*)d_in[1];
    const int*   spk      = (const int*)d_in[2];
    const float* emb_u    = (const float*)d_in[3];
    const float* emb_r    = (const float*)d_in[4];
    const float* uWih = (const float*)d_in[5];
    const float* uWhh = (const float*)d_in[6];
    const float* ubih = (const float*)d_in[7];
    const float* ubhh = (const float*)d_in[8];
    const float* cWih = (const float*)d_in[9];
    const float* cWhh = (const float*)d_in[10];
    const float* cbih = (const float*)d_in[11];
    const float* cbhh = (const float*)d_in[12];
    const float* rWih = (const float*)d_in[13];
    const float* rWhh = (const float*)d_in[14];
    const float* rbih = (const float*)d_in[15];
    const float* rbhh = (const float*)d_in[16];
    const float* sWih = (const float*)d_in[17];
    const float* sWhh = (const float*)d_in[18];
    const float* sbih = (const float*)d_in[19];
    const float* sbhh = (const float*)d_in[20];
    float* out = (float*)d_out;

    void *p;
    float *tab, *GIu, *GIc, *GIr, *hall, *hc, *hspk, *cin;
    float *WTu_i, *WTc_i, *WTc_h, *WTr_i, *WTs_i, *WTs_h;
    __nv_bfloat16 *h_hi, *h_lo, *Wu_hi, *Wu_lo, *Wr_hi, *Wr_lo;
    int *toku, *tokr, *pres;
    cudaGetSymbolAddress(&p, g_tables); tab  = (float*)p;
    cudaGetSymbolAddress(&p, g_GIu);    GIu  = (float*)p;
    cudaGetSymbolAddress(&p, g_GIc);    GIc  = (float*)p;
    cudaGetSymbolAddress(&p, g_GIr);    GIr  = (float*)p;
    cudaGetSymbolAddress(&p, g_hall);   hall = (float*)p;
    cudaGetSymbolAddress(&p, g_hbf_hi); h_hi = (__nv_bfloat16*)p;
    cudaGetSymbolAddress(&p, g_hbf_lo); h_lo = (__nv_bfloat16*)p;
    cudaGetSymbolAddress(&p, g_hc);     hc   = (float*)p;
    cudaGetSymbolAddress(&p, g_hspk);   hspk = (float*)p;
    cudaGetSymbolAddress(&p, g_ctxin);  cin  = (float*)p;
    cudaGetSymbolAddress(&p, g_WTu_i);  WTu_i = (float*)p;
    cudaGetSymbolAddress(&p, g_WTc_i);  WTc_i = (float*)p;
    cudaGetSymbolAddress(&p, g_WTc_h);  WTc_h = (float*)p;
    cudaGetSymbolAddress(&p, g_WTr_i);  WTr_i = (float*)p;
    cudaGetSymbolAddress(&p, g_WTs_i);  WTs_i = (float*)p;
    cudaGetSymbolAddress(&p, g_WTs_h);  WTs_h = (float*)p;
    cudaGetSymbolAddress(&p, g_Wubf_hi); Wu_hi = (__nv_bfloat16*)p;
    cudaGetSymbolAddress(&p, g_Wubf_lo); Wu_lo = (__nv_bfloat16*)p;
    cudaGetSymbolAddress(&p, g_Wrbf_hi); Wr_hi = (__nv_bfloat16*)p;
    cudaGetSymbolAddress(&p, g_Wrbf_lo); Wr_lo = (__nv_bfloat16*)p;
    cudaGetSymbolAddress(&p, g_toku);   toku = (int*)p;
    cudaGetSymbolAddress(&p, g_tokr);   tokr = (int*)p;
    cudaGetSymbolAddress(&p, g_present); pres = (int*)p;

    cudaFuncSetAttribute(step_mma_kernel, cudaFuncAttributeMaxDynamicSharedMemorySize, SMEM_STEP);

    // 1. prep
    prep_kernel<<<(PREP_TOTAL + 255)/256, 256>>>(
        context, response, spk,
        uWih, uWhh, cWih, cWhh, rWih, rWhh, sWih, sWhh,
        WTu_i, WTc_i, WTc_h, WTr_i, WTs_i, WTs_h,
        Wu_hi, Wu_lo, Wr_hi, Wr_lo,
        toku, tokr, hall, h_hi, h_lo, hc, hspk, pres);

    // 2. fused GEMMs + MT19937
    mega_gemm_kernel<<<7801, 256>>>(emb_u, emb_r, toku, tokr,
                                    WTu_i, ubih, WTr_i, rbih, GIu, GIr, tab);

    // 3. utterance + response recurrences via mma.sync bf16-split
    for (int t = 0; t < T_; t++)
        step_mma_kernel<<<208, 256, SMEM_STEP>>>(GIu, GIr, hall, h_hi, h_lo,
                                                 Wu_hi, Wu_lo, Wr_hi, Wr_lo,
                                                 ubhh, rbhh, out + OFF_RESPOUT, t);

    // 4. context input + GEMM
    ctx_in_kernel<<<(MC_*2*H_ + 255)/256, 256>>>(hall, tab, spk, cin);
    gemm_ctx_kernel<<<150, 256>>>(cin, WTc_i, cbih, GIc);

    // 5. pipelined ctx + speaker chains (R2 form)
    for (int i = 0; i <= S_; i++)
        step_cs_kernel<<<32, 256>>>(GIc, hc, WTc_h, cbhh, out + OFF_CTXOUT,
                                    hspk, spk, WTs_i, WTs_h, sbih, sbhh, i);

    // 6. epilogue
    epilogue_kernel<<<(EPI_TOTAL + 255)/256, 256>>>(out, hall, hspk, pres);
}

// round 5
// speedup vs baseline: 1.4915x; 1.2927x over previous
#include <cuda_runtime.h>
#include <cuda_bf16.h>
#include <math.h>

typedef unsigned long long u64;
typedef unsigned int u32;

// ---------------- constants ----------------
#define B_  64
#define S_  50
#define T_  50
#define R_  2
#define H_  256
#define NU_ (B_*S_)          // 3200
#define NR_ (B_*R_)          // 128
#define NALL_ (NU_+NR_)      // 3328
#define MU_ (T_*NU_)         // 160000
#define MR_ (T_*NR_)         // 6400
#define MC_ (S_*B_)          // 3200
#define TAB_N (B_*(S_+1)*H_) // 835584

// output offsets (f32 elements)
#define OFF_CTXOUT   0
#define OFF_CTXHID   819200
#define OFF_RESPOUT  835584
#define OFF_RESPHID  2473984
#define OFF_SPKEMB   2506752
#define OFF_MASK     3342336

// ---------------- static device scratch ----------------
__device__ float g_tables[TAB_N];
__device__ float g_GIu[(size_t)MU_*768];
__device__ float g_GIc[(size_t)MC_*768];
__device__ float g_GIr[(size_t)MR_*768];
__device__ float g_hall[NALL_*H_];
__device__ __nv_bfloat16 g_hbf_hi[NALL_*H_];
__device__ __nv_bfloat16 g_hbf_lo[NALL_*H_];
__device__ float g_hc[B_*H_];
__device__ float g_hspk[B_*(S_+1)*H_];
__device__ float g_ctxin[MC_*2*H_];
__device__ float g_WTu_i[H_*768];
__device__ float g_WTc_i[2*H_*768], g_WTc_h[H_*768];
__device__ float g_WTr_i[H_*768];
__device__ float g_WTs_i[H_*768],  g_WTs_h[H_*768];
__device__ __nv_bfloat16 g_Wubf_hi[768*H_], g_Wubf_lo[768*H_];   // native [768,256]
__device__ __nv_bfloat16 g_Wrbf_hi[768*H_], g_Wrbf_lo[768*H_];
__device__ int   g_toku[MU_];
__device__ int   g_tokr[MR_];
__device__ int   g_present[B_*(S_+1)];

// ---------------- helpers ----------------
__device__ __forceinline__ u64 pack2(float lo, float hi) {
    u64 r; asm("mov.b64 %0, {%1,%2};" : "=l"(r) : "f"(lo), "f"(hi)); return r;
}
__device__ __forceinline__ void unpack2(u64 a, float& lo, float& hi) {
    asm("mov.b64 {%0,%1}, %2;" : "=f"(lo), "=f"(hi) : "l"(a));
}
__device__ __forceinline__ u64 ffma2(u64 a, u64 b, u64 c) {
    u64 d; asm("fma.rn.f32x2 %0, %1, %2, %3;" : "=l"(d) : "l"(a), "l"(b), "l"(c)); return d;
}
__device__ __forceinline__ void cp_async16(void* dst_smem, const void* src) {
    unsigned sa = (unsigned)__cvta_generic_to_shared(dst_smem);
    asm volatile("cp.async.ca.shared.global [%0], [%1], 16;" :: "r"(sa), "l"(src));
}
__device__ __forceinline__ void cp_commit() { asm volatile("cp.async.commit_group;"); }
template<int N> __device__ __forceinline__ void cp_wait() { asm volatile("cp.async.wait_group %0;" :: "n"(N)); }
__device__ __forceinline__ void ldx4(u32* r, u32 addr) {
    asm volatile("ldmatrix.sync.aligned.m8n8.x4.shared.b16 {%0,%1,%2,%3}, [%4];"
        : "=r"(r[0]), "=r"(r[1]), "=r"(r[2]), "=r"(r[3]) : "r"(addr));
}
__device__ __forceinline__ void mma_bf16(float* c, const u32* a, u32 b0, u32 b1) {
    asm volatile(
        "mma.sync.aligned.m16n8k16.row.col.f32.bf16.bf16.f32 "
        "{%0,%1,%2,%3}, {%4,%5,%6,%7}, {%8,%9}, {%0,%1,%2,%3};"
        : "+f"(c[0]), "+f"(c[1]), "+f"(c[2]), "+f"(c[3])
        : "r"(a[0]), "r"(a[1]), "r"(a[2]), "r"(a[3]), "r"(b0), "r"(b1));
}

// ---------------- MT19937 (NumPy-exact) ----------------
__device__ __forceinline__ unsigned mt_twist_fn(unsigned u, unsigned v) {
    unsigned y = (u & 0x80000000u) | (v & 0x7fffffffu);
    return (y >> 1) ^ ((v & 1u) ? 0x9908b0dfu : 0u);
}
__device__ __forceinline__ unsigned mt_temper(unsigned y) {
    y ^= y >> 11; y ^= (y << 7) & 0x9d2c5680u; y ^= (y << 15) & 0xefc60000u; y ^= y >> 18;
    return y;
}
__device__ void mt_body(float* __restrict__ tables, unsigned* bufA, unsigned* bufB) {
    const int tid = threadIdx.x;
    if (tid == 0) {
        unsigned s = 1u; bufA[0] = s;
        for (int i = 1; i < 624; i++) { s = 1812433253u * (s ^ (s >> 30)) + (unsigned)i; bufA[i] = s; }
    }
    __syncthreads();
    unsigned* cur = bufA; unsigned* nxt = bufB;
    const int NTW = (2*TAB_N + 623) / 624;
    for (int tw = 0; tw < NTW; tw++) {
        if (tid < 227) nxt[tid] = cur[tid + 397] ^ mt_twist_fn(cur[tid], cur[tid + 1]);
        __syncthreads();
        if (tid < 227) { int i = 227 + tid; nxt[i] = nxt[i - 227] ^ mt_twist_fn(cur[i], cur[i + 1]); }
        __syncthreads();
        if (tid < 170) {
            int i = 454 + tid;
            unsigned v = (i == 623) ? nxt[0] : cur[i + 1];
            nxt[i] = nxt[i - 227] ^ mt_twist_fn(cur[i], v);
        }
        __syncthreads();
        for (int o = tid; o < 312; o += 256) {
            int outIdx = tw * 312 + o;
            if (outIdx < TAB_N) {
                unsigned a  = mt_temper(nxt[2*o])   >> 5;
                unsigned bv = mt_temper(nxt[2*o+1]) >> 6;
                tables[outIdx] = (float)(((double)a * 67108864.0 + (double)bv) * (1.0 / 9007199254740992.0));
            }
        }
        __syncthreads();
        unsigned* t2 = cur; cur = nxt; nxt = t2;
    }
}

// ---------------- fp32 GEMM body: BM=BN=128, BK=16, 8x8/thread, FFMA2 ----------------
__device__ __forceinline__ void gemm_body(
    const float* __restrict__ A, const int* __restrict__ toks, const float* __restrict__ emb,
    const float* __restrict__ BT, const float* __restrict__ bias, float* __restrict__ C,
    int m0, int n0, int K, float* As, float* Bs)
{
    const int tid  = threadIdx.x;
    const int arow = tid >> 2;
    const int akc  = (tid & 3) << 2;
    const int bk   = tid >> 4;
    const int bc   = (tid & 15) << 3;
    const int tr   = tid >> 4;
    const int tc   = tid & 15;

    const float* arp0;
    const float* arp1;
    {
        int gm0 = m0 + arow, gm1 = m0 + arow + 64;
        arp0 = toks ? (emb + (size_t)__ldg(toks + gm0) * K) : (A + (size_t)gm0 * K);
        arp1 = toks ? (emb + (size_t)__ldg(toks + gm1) * K) : (A + (size_t)gm1 * K);
    }
    float4 ra0 = *(const float4*)(arp0 + akc);
    float4 ra1 = *(const float4*)(arp1 + akc);
    float4 rb0 = *(const float4*)(BT + (size_t)bk * 768 + n0 + bc);
    float4 rb1 = *(const float4*)(BT + (size_t)bk * 768 + n0 + bc + 4);
    {
        As[(akc+0)*128 + arow] = ra0.x; As[(akc+1)*128 + arow] = ra0.y;
        As[(akc+2)*128 + arow] = ra0.z; As[(akc+3)*128 + arow] = ra0.w;
        As[(akc+0)*128 + arow+64] = ra1.x; As[(akc+1)*128 + arow+64] = ra1.y;
        As[(akc+2)*128 + arow+64] = ra1.z; As[(akc+3)*128 + arow+64] = ra1.w;
        *(float4*)(Bs + bk*128 + bc)     = rb0;
        *(float4*)(Bs + bk*128 + bc + 4) = rb1;
    }
    __syncthreads();

    u64 acc[8][4];
    #pragma unroll
    for (int i = 0; i < 8; i++)
        #pragma unroll
        for (int j = 0; j < 4; j++) acc[i][j] = 0ull;

    int buf = 0;
    for (int k0 = 16; k0 <= K; k0 += 16) {
        const bool more = (k0 < K);
        if (more) {
            ra0 = *(const float4*)(arp0 + k0 + akc);
            ra1 = *(const float4*)(arp1 + k0 + akc);
            rb0 = *(const float4*)(BT + (size_t)(k0 + bk) * 768 + n0 + bc);
            rb1 = *(const float4*)(BT + (size_t)(k0 + bk) * 768 + n0 + bc + 4);
        }
        const float* Asb = As + buf * 2048;
        const float* Bsb = Bs + buf * 2048;
        #pragma unroll
        for (int kk = 0; kk < 16; kk++) {
            float4 av0 = *(const float4*)(Asb + kk*128 + tr*8);
            float4 av1 = *(const float4*)(Asb + kk*128 + tr*8 + 4);
            u64 bb0 = *(const u64*)(Bsb + kk*128 + tc*4);
            u64 bb1 = *(const u64*)(Bsb + kk*128 + tc*4 + 2);
            u64 bb2 = *(const u64*)(Bsb + kk*128 + 64 + tc*4);
            u64 bb3 = *(const u64*)(Bsb + kk*128 + 64 + tc*4 + 2);
            float av[8] = {av0.x, av0.y, av0.z, av0.w, av1.x, av1.y, av1.z, av1.w};
            #pragma unroll
            for (int i = 0; i < 8; i++) {
                u64 aa = pack2(av[i], av[i]);
                acc[i][0] = ffma2(aa, bb0, acc[i][0]);
                acc[i][1] = ffma2(aa, bb1, acc[i][1]);
                acc[i][2] = ffma2(aa, bb2, acc[i][2]);
                acc[i][3] = ffma2(aa, bb3, acc[i][3]);
            }
        }
        if (more) {
            float* Asb1 = As + (buf ^ 1) * 2048;
            float* Bsb1 = Bs + (buf ^ 1) * 2048;
            Asb1[(akc+0)*128 + arow] = ra0.x; Asb1[(akc+1)*128 + arow] = ra0.y;
            Asb1[(akc+2)*128 + arow] = ra0.z; Asb1[(akc+3)*128 + arow] = ra0.w;
            Asb1[(akc+0)*128 + arow+64] = ra1.x; Asb1[(akc+1)*128 + arow+64] = ra1.y;
            Asb1[(akc+2)*128 + arow+64] = ra1.z; Asb1[(akc+3)*128 + arow+64] = ra1.w;
            *(float4*)(Bsb1 + bk*128 + bc)     = rb0;
            *(float4*)(Bsb1 + bk*128 + bc + 4) = rb1;
        }
        __syncthreads();
        buf ^= 1;
    }

    float4 bba = *(const float4*)(bias + n0 + tc*4);
    float4 bbb = *(const float4*)(bias + n0 + 64 + tc*4);
    #pragma unroll
    for (int i = 0; i < 8; i++) {
        int gm = m0 + tr*8 + i;
        float x0,x1,x2,x3,y0,y1,y2,y3;
        unpack2(acc[i][0], x0, x1); unpack2(acc[i][1], x2, x3);
        unpack2(acc[i][2], y0, y1); unpack2(acc[i][3], y2, y3);
        float4 o0 = make_float4(x0+bba.x, x1+bba.y, x2+bba.z, x3+bba.w);
        float4 o1 = make_float4(y0+bbb.x, y1+bbb.y, y2+bbb.z, y3+bbb.w);
        *(float4*)(C + (size_t)gm*768 + n0 + tc*4)      = o0;
        *(float4*)(C + (size_t)gm*768 + n0 + 64 + tc*4) = o1;
    }
}

__global__ __launch_bounds__(256) void mega_gemm_kernel(
    const float* __restrict__ emb_u, const float* __restrict__ emb_r,
    const int* __restrict__ toku, const int* __restrict__ tokr,
    const float* __restrict__ WTu_i, const float* __restrict__ ubih,
    const float* __restrict__ WTr_i, const float* __restrict__ rbih,
    float* __restrict__ GIu, float* __restrict__ GIr, float* __restrict__ tables)
{
    __shared__ float As[2*16*128];
    __shared__ float Bs[2*16*128];
    __shared__ unsigned mtA[624], mtB[624];
    int b = blockIdx.x;
    if (b < 7500) {
        int mb = b % 1250, nb = b / 1250;
        gemm_body(nullptr, toku, emb_u, WTu_i, ubih, GIu, mb*128, nb*128, 256, As, Bs);
    } else if (b < 7800) {
        int b2 = b - 7500;
        int mb = b2 % 50, nb = b2 / 50;
        gemm_body(nullptr, tokr, emb_r, WTr_i, rbih, GIr, mb*128, nb*128, 256, As, Bs);
    } else {
        mt_body(tables, mtA, mtB);
    }
}

__global__ __launch_bounds__(256) void gemm_ctx_kernel(
    const float* __restrict__ cin, const float* __restrict__ WTc_i,
    const float* __restrict__ cbih, float* __restrict__ GIc)
{
    __shared__ float As[2*16*128];
    __shared__ float Bs[2*16*128];
    int mb = blockIdx.x % 25, nb = blockIdx.x / 25;
    gemm_body(cin, nullptr, nullptr, WTc_i, cbih, GIc, mb*128, nb*128, 512, As, Bs);
}

// ---------------- smem-staged mma GRU step ----------------
// M=32 rows/block, grid 104 (100 utter + 4 resp). 8 warps: mh = wid>>2, nq = wid&3.
// W staged per 16-wide k-tile via cp.async (hi+lo), double-buffered; ldmatrix fragments.
#define HP_ 264                 // h smem pitch (bf16)
#define WP_ 24                  // W smem pitch (bf16)
#define WTILE_ (768*WP_)        // bf16 elems per W tile
#define SMEM_STEP (2*32*HP_*2 + 2*2*WTILE_*2)   // 33792 + 147456 = 181248 B

__global__ __launch_bounds__(256, 1) void step_mma_kernel(
    const float* __restrict__ GIu, const float* __restrict__ GIr,
    float* __restrict__ hall,
    __nv_bfloat16* __restrict__ h_hi, __nv_bfloat16* __restrict__ h_lo,
    const __nv_bfloat16* __restrict__ Wu_hi, const __nv_bfloat16* __restrict__ Wu_lo,
    const __nv_bfloat16* __restrict__ Wr_hi, const __nv_bfloat16* __restrict__ Wr_lo,
    const float* __restrict__ ubhh, const float* __restrict__ rbhh,
    float* __restrict__ respout, int t)
{
    extern __shared__ char smem[];
    __nv_bfloat16* h_hi_s = (__nv_bfloat16*)smem;           // [32][HP_]
    __nv_bfloat16* h_lo_s = h_hi_s + 32*HP_;
    __nv_bfloat16* Wbuf   = h_lo_s + 32*HP_;                // 2 bufs x (hi tile + lo tile)
    float* Cs = (float*)smem;                               // epilogue overlap [32][776]

    const int bx = blockIdx.x;
    const bool isResp = bx >= 100;
    const int row0 = isResp ? NU_ + (bx - 100)*32 : bx*32;
    const __nv_bfloat16* Whi = isResp ? Wr_hi : Wu_hi;
    const __nv_bfloat16* Wlo = isResp ? Wr_lo : Wu_lo;
    const float* bhh = isResp ? rbhh : ubhh;
    const float* GI = isResp ? (GIr + (size_t)t*NR_*768 + (size_t)(bx - 100)*32*768)
                             : (GIu + (size_t)t*NU_*768 + (size_t)bx*32*768);

    const int tid = threadIdx.x;
    const int wid = tid >> 5, lane = tid & 31;
    const int mh = wid >> 2;           // 0,1 -> rows mh*16..+15
    const int n0 = (wid & 3) * 192;    // 192 cols per warp

    // ---- stage h (hi+lo) into smem ----
    for (int i = tid; i < 32*128; i += 256) {
        int r = i >> 7, c2 = (i & 127) * 2;
        *(u32*)(h_hi_s + r*HP_ + c2) = *(const u32*)(h_hi + (size_t)(row0 + r)*256 + c2);
        *(u32*)(h_lo_s + r*HP_ + c2) = *(const u32*)(h_lo + (size_t)(row0 + r)*256 + c2);
    }
    // ---- prefetch W k-tile 0 ----
    {
        __nv_bfloat16* dhi = Wbuf;
        __nv_bfloat16* dlo = Wbuf + WTILE_;
        for (int i = tid; i < 1536; i += 256) {
            int row = i >> 1, half = (i & 1) * 8;
            cp_async16(dhi + row*WP_ + half, Whi + (size_t)row*256 + half);
            cp_async16(dlo + row*WP_ + half, Wlo + (size_t)row*256 + half);
        }
        cp_commit();
    }

    float acc[24][4];
    #pragma unroll
    for (int nt = 0; nt < 24; nt++)
        #pragma unroll
        for (int i = 0; i < 4; i++) acc[nt][i] = 0.f;

    // fragment address components
    const u32 a_off = (u32)((mh*16 + ((lane>>3)&1)*8 + (lane&7))*HP_*2 + (lane>>4)*16);
    const u32 ahi_base = (u32)__cvta_generic_to_shared(h_hi_s) + a_off;
    const u32 alo_base = (u32)__cvta_generic_to_shared(h_lo_s) + a_off;
    const int b_pair  = lane >> 4;
    const int b_khalf = ((lane >> 3) & 1) * 16;
    const int b_r     = lane & 7;
    const u32 wbuf_base = (u32)__cvta_generic_to_shared(Wbuf);

    for (int kt = 0; kt < 16; kt++) {
        const int buf = kt & 1;
        if (kt < 15) {
            __nv_bfloat16* dhi = Wbuf + (buf ^ 1) * 2*WTILE_;
            __nv_bfloat16* dlo = dhi + WTILE_;
            const __nv_bfloat16* shi = Whi + (kt + 1)*16;
            const __nv_bfloat16* slo = Wlo + (kt + 1)*16;
            for (int i = tid; i < 1536; i += 256) {
                int row = i >> 1, half = (i & 1) * 8;
                cp_async16(dhi + row*WP_ + half, shi + (size_t)row*256 + half);
                cp_async16(dlo + row*WP_ + half, slo + (size_t)row*256 + half);
            }
            cp_commit();
            cp_wait<1>();
        } else {
            cp_wait<0>();
        }
        __syncthreads();

        u32 ah[4], al[4];
        ldx4(ah, ahi_base + kt*32);
        ldx4(al, alo_base + kt*32);
        const u32 bhi_base = wbuf_base + buf * (2*WTILE_*2);
        const u32 blo_base = bhi_base + WTILE_*2;
        #pragma unroll
        for (int nt = 0; nt < 24; nt += 2) {
            u32 ro = (u32)((n0 + (nt + b_pair)*8 + b_r) * (WP_*2) + b_khalf);
            u32 bh[4], bl[4];
            ldx4(bh, bhi_base + ro);
            ldx4(bl, blo_base + ro);
            mma_bf16(acc[nt],   ah, bh[0], bh[1]);
            mma_bf16(acc[nt],   al, bh[0], bh[1]);
            mma_bf16(acc[nt],   ah, bl[0], bl[1]);
            mma_bf16(acc[nt+1], ah, bh[2], bh[3]);
            mma_bf16(acc[nt+1], al, bh[2], bh[3]);
            mma_bf16(acc[nt+1], ah, bl[2], bl[3]);
        }
        __syncthreads();
    }

    // ---- write C fragments to smem (overlaps h/W buffers; safe after sync) ----
    {
        const int g = lane >> 2, tg = lane & 3;
        const int rl = mh*16 + g;
        #pragma unroll
        for (int nt = 0; nt < 24; nt++) {
            int c = n0 + nt*8 + tg*2;
            Cs[rl*776 + c]         = acc[nt][0];
            Cs[rl*776 + c + 1]     = acc[nt][1];
            Cs[(rl+8)*776 + c]     = acc[nt][2];
            Cs[(rl+8)*776 + c + 1] = acc[nt][3];
        }
    }
    __syncthreads();

    // ---- gate epilogue: thread j handles col j for 32 rows ----
    const float br = bhh[tid], bz = bhh[tid+256], bn = bhh[tid+512];
    #pragma unroll 4
    for (int r = 0; r < 32; r++) {
        const int grow = row0 + r;
        const float* gi = GI + (size_t)r*768;
        float aR = Cs[r*776 + tid];
        float aZ = Cs[r*776 + tid + 256];
        float aN = Cs[r*776 + tid + 512];
        float ir = gi[tid], iz = gi[tid+256], inn = gi[tid+512];
        float rg = 1.f / (1.f + expf(-(ir + aR + br)));
        float z  = 1.f / (1.f + expf(-(iz + aZ + bz)));
        float nn = tanhf(inn + rg * (aN + bn));
        float hold = hall[(size_t)grow*256 + tid];
        float hnew = (1.f - z) * nn + z * hold;
        hall[(size_t)grow*256 + tid] = hnew;
        __nv_bfloat16 hi = __float2bfloat16(hnew);
        h_hi[(size_t)grow*256 + tid] = hi;
        h_lo[(size_t)grow*256 + tid] = __float2bfloat16(hnew - __bfloat162float(hi));
        if (isResp) {
            int n = grow - NU_;
            int rr = n & 1, bb = n >> 1;
            respout[(((size_t)rr*T_ + t)*B_ + bb)*256 + tid] = hnew;
        }
    }
}

// ---------------- small GRU body (ctx chain) ----------------
template<int ROWS>
__device__ __forceinline__ void gru_body(
    const float* __restrict__ GI, float* __restrict__ h,
    const float* __restrict__ WT, const float* __restrict__ bhh,
    float* __restrict__ outp, int out_mode, int t, int row0, float* hs)
{
    constexpr int PS = ROWS + 2;
    const int tid = threadIdx.x;
    for (int idx = tid; idx < ROWS*256; idx += 256) {
        int r = idx >> 8, k = idx & 255;
        hs[k*PS + r] = h[(size_t)(row0 + r)*256 + k];
    }
    __syncthreads();
    u64 aR[ROWS/2], aZ[ROWS/2], aN[ROWS/2];
    #pragma unroll
    for (int p = 0; p < ROWS/2; p++) { aR[p]=0ull; aZ[p]=0ull; aN[p]=0ull; }
    const float* Wp = WT + tid;
    #pragma unroll 4
    for (int k = 0; k < 256; k++) {
        float w0 = __ldg(Wp + (size_t)k*768);
        float w1 = __ldg(Wp + (size_t)k*768 + 256);
        float w2 = __ldg(Wp + (size_t)k*768 + 512);
        u64 W0 = pack2(w0, w0), W1 = pack2(w1, w1), W2 = pack2(w2, w2);
        const u64* hp = (const u64*)(hs + k*PS);
        #pragma unroll
        for (int p = 0; p < ROWS/2; p++) {
            u64 hv = hp[p];
            aR[p] = ffma2(hv, W0, aR[p]);
            aZ[p] = ffma2(hv, W1, aZ[p]);
            aN[p] = ffma2(hv, W2, aN[p]);
        }
    }
    const float br = bhh[tid], bz = bhh[tid+256], bn = bhh[tid+512];
    #pragma unroll
    for (int p = 0; p < ROWS/2; p++) {
        float aRl,aRh,aZl,aZh,aNl,aNh;
        unpack2(aR[p], aRl, aRh); unpack2(aZ[p], aZl, aZh); unpack2(aN[p], aNl, aNh);
        #pragma unroll
        for (int q = 0; q < 2; q++) {
            int r = 2*p + q;
            float accR = q ? aRh : aRl;
            float accZ = q ? aZh : aZl;
            float accN = q ? aNh : aNl;
            int grow = row0 + r;
            const float* gi = GI + (size_t)grow*768;
            float ir = gi[tid], iz = gi[tid+256], inn = gi[tid+512];
            float rg = 1.f / (1.f + expf(-(ir + accR + br)));
            float z  = 1.f / (1.f + expf(-(iz + accZ + bz)));
            float nn = tanhf(inn + rg * (accN + bn));
            float hold = hs[tid*PS + r];
            float hnew = (1.f - z) * nn + z * hold;
            h[(size_t)grow*256 + tid] = hnew;
            if (out_mode == 1) outp[(size_t)grow*256 + tid] = hnew;
        }
    }
}

// ---------------- speaker step body ----------------
__device__ void spk_body(const float* __restrict__ ctxout_s,
                         float* __restrict__ hspk, const int* __restrict__ spk,
                         const float* __restrict__ WTi, const float* __restrict__ WTh,
                         const float* __restrict__ bih, const float* __restrict__ bhh,
                         int s, int b0, float* sm)
{
    const int tid = threadIdx.x;
    float* cs  = sm;
    float* hsv = sm + 256*6;
    int id[4];
    #pragma unroll
    for (int r = 0; r < 4; r++) id[r] = spk[(b0 + r)*S_ + s];
    for (int idx = tid; idx < 4*256; idx += 256) {
        int r = idx >> 8, k = idx & 255;
        cs[k*6 + r]  = ctxout_s[(size_t)(b0 + r)*256 + k];
        hsv[k*6 + r] = hspk[((size_t)(b0 + r)*(S_+1) + id[r])*256 + k];
    }
    __syncthreads();
    u64 iR[2]={0ull,0ull}, iZ[2]={0ull,0ull}, iN[2]={0ull,0ull};
    u64 hR[2]={0ull,0ull}, hZ[2]={0ull,0ull}, hN[2]={0ull,0ull};
    #pragma unroll 2
    for (int k = 0; k < 256; k++) {
        float wi0 = __ldg(WTi + (size_t)k*768 + tid);
        float wi1 = __ldg(WTi + (size_t)k*768 + 256 + tid);
        float wi2 = __ldg(WTi + (size_t)k*768 + 512 + tid);
        float wh0 = __ldg(WTh + (size_t)k*768 + tid);
        float wh1 = __ldg(WTh + (size_t)k*768 + 256 + tid);
        float wh2 = __ldg(WTh + (size_t)k*768 + 512 + tid);
        u64 Wi0 = pack2(wi0,wi0), Wi1 = pack2(wi1,wi1), Wi2 = pack2(wi2,wi2);
        u64 Wh0 = pack2(wh0,wh0), Wh1 = pack2(wh1,wh1), Wh2 = pack2(wh2,wh2);
        const u64* cp = (const u64*)(cs + k*6);
        const u64* hp = (const u64*)(hsv + k*6);
        #pragma unroll
        for (int p = 0; p < 2; p++) {
            u64 cv = cp[p], hv = hp[p];
            iR[p] = ffma2(cv, Wi0, iR[p]); iZ[p] = ffma2(cv, Wi1, iZ[p]); iN[p] = ffma2(cv, Wi2, iN[p]);
            hR[p] = ffma2(hv, Wh0, hR[p]); hZ[p] = ffma2(hv, Wh1, hZ[p]); hN[p] = ffma2(hv, Wh2, hN[p]);
        }
    }
    const float bi0 = bih[tid], bi1 = bih[tid+256], bi2 = bih[tid+512];
    const float bh0 = bhh[tid], bh1 = bhh[tid+256], bh2 = bhh[tid+512];
    #pragma unroll
    for (int p = 0; p < 2; p++) {
        float iRl,iRh,iZl,iZh,iNl,iNh,hRl,hRh,hZl,hZh,hNl,hNh;
        unpack2(iR[p],iRl,iRh); unpack2(iZ[p],iZl,iZh); unpack2(iN[p],iNl,iNh);
        unpack2(hR[p],hRl,hRh); unpack2(hZ[p],hZl,hZh); unpack2(hN[p],hNl,hNh);
        #pragma unroll
        for (int q = 0; q < 2; q++) {
            int r = 2*p + q;
            float giR = (q ? iRh : iRl) + bi0;
            float giZ = (q ? iZh : iZl) + bi1;
            float giN = (q ? iNh : iNl) + bi2;
            float ghR = (q ? hRh : hRl) + bh0;
            float ghZ = (q ? hZh : hZl) + bh1;
            float ghN = (q ? hNh : hNl) + bh2;
            float rg = 1.f / (1.f + expf(-(giR + ghR)));
            float z  = 1.f / (1.f + expf(-(giZ + ghZ)));
            float nn = tanhf(giN + rg * ghN);
            float hold = hsv[tid*6 + r];
            float hnew = (1.f - z) * nn + z * hold;
            hspk[((size_t)(b0 + r)*(S_+1) + id[r])*256 + tid] = hnew;
        }
    }
}

__global__ __launch_bounds__(256) void step_cs_kernel(
    const float* __restrict__ GIc, float* __restrict__ hc,
    const float* __restrict__ WTc_h, const float* __restrict__ cbhh,
    float* __restrict__ ctxout, float* __restrict__ hspk, const int* __restrict__ spk,
    const float* __restrict__ WTs_i, const float* __restrict__ WTs_h,
    const float* __restrict__ sbih, const float* __restrict__ sbhh, int i)
{
    __shared__ float sm[256*12];
    if (blockIdx.x < 16) {
        if (i < S_)
            gru_body<4>(GIc + (size_t)i*B_*768, hc, WTc_h, cbhh,
                        ctxout + (size_t)i*B_*256, 1, i, blockIdx.x*4, sm);
    } else {
        int s = i - 1;
        if (s >= 0)
            spk_body(ctxout + (size_t)s*B_*256, hspk, spk, WTs_i, WTs_h, sbih, sbhh,
                     s, (blockIdx.x - 16)*4, sm);
    }
}

// ---------------- prep kernel ----------------
#define SEG_T256 196608
#define SEG_T512 393216
#define PREP_TOTAL (196608*5 + 393216 + 196608*2 + 160000 + 6400 + 851968 + 16384 + 835584 + 3264)

__global__ void prep_kernel(
    const int* __restrict__ context, const int* __restrict__ response, const int* __restrict__ spk,
    const float* __restrict__ uWih, const float* __restrict__ uWhh,
    const float* __restrict__ cWih, const float* __restrict__ cWhh,
    const float* __restrict__ rWih, const float* __restrict__ rWhh,
    const float* __restrict__ sWih, const float* __restrict__ sWhh,
    float* __restrict__ WTu_i,
    float* __restrict__ WTc_i, float* __restrict__ WTc_h,
    float* __restrict__ WTr_i,
    float* __restrict__ WTs_i, float* __restrict__ WTs_h,
    __nv_bfloat16* __restrict__ Wu_hi, __nv_bfloat16* __restrict__ Wu_lo,
    __nv_bfloat16* __restrict__ Wr_hi, __nv_bfloat16* __restrict__ Wr_lo,
    int* __restrict__ toku, int* __restrict__ tokr,
    float* __restrict__ hall, __nv_bfloat16* __restrict__ h_hi, __nv_bfloat16* __restrict__ h_lo,
    float* __restrict__ hc, float* __restrict__ hspk, int* __restrict__ pres)
{
    long i = (long)blockIdx.x*256 + threadIdx.x;
    if (i >= PREP_TOTAL) return;
    if (i < SEG_T256) { int g = i >> 8, k = i & 255; WTu_i[k*768 + g] = uWih[i]; return; }
    i -= SEG_T256;
    if (i < SEG_T512) { int g = (int)(i / 512), k = (int)(i % 512); WTc_i[k*768 + g] = cWih[i]; return; }
    i -= SEG_T512;
    if (i < SEG_T256) { int g = i >> 8, k = i & 255; WTc_h[k*768 + g] = cWhh[i]; return; }
    i -= SEG_T256;
    if (i < SEG_T256) { int g = i >> 8, k = i & 255; WTr_i[k*768 + g] = rWih[i]; return; }
    i -= SEG_T256;
    if (i < SEG_T256) { int g = i >> 8, k = i & 255; WTs_i[k*768 + g] = sWih[i]; return; }
    i -= SEG_T256;
    if (i < SEG_T256) { int g = i >> 8, k = i & 255; WTs_h[k*768 + g] = sWhh[i]; return; }
    i -= SEG_T256;
    if (i < SEG_T256) {
        float w = uWhh[i];
        __nv_bfloat16 hi = __float2bfloat16(w);
        Wu_hi[i] = hi;
        Wu_lo[i] = __float2bfloat16(w - __bfloat162float(hi));
        return;
    }
    i -= SEG_T256;
    if (i < SEG_T256) {
        float w = rWhh[i];
        __nv_bfloat16 hi = __float2bfloat16(w);
        Wr_hi[i] = hi;
        Wr_lo[i] = __float2bfloat16(w - __bfloat162float(hi));
        return;
    }
    i -= SEG_T256;
    if (i < MU_) { int t = (int)(i / NU_), n = (int)(i % NU_); toku[i] = context[n*T_ + t]; return; }
    i -= MU_;
    if (i < MR_) { int t = (int)(i / NR_), n = (int)(i % NR_); tokr[i] = response[n*T_ + t]; return; }
    i -= MR_;
    if (i < NALL_*H_) { hall[i] = 0.f; h_hi[i] = __float2bfloat16(0.f); h_lo[i] = __float2bfloat16(0.f); return; }
    i -= NALL_*H_;
    if (i < B_*H_) { hc[i] = 0.f; return; }
    i -= B_*H_;
    if (i < B_*(S_+1)*H_) { hspk[i] = 0.f; return; }
    i -= B_*(S_+1)*H_;
    {
        int b = (int)(i / (S_+1)), a = (int)(i % (S_+1));
        int p = 0;
        for (int s = 0; s < S_; s++) p |= (spk[b*S_ + s] == a);
        pres[i] = p;
    }
}

// ---------------- ctx input gather ----------------
__global__ void ctx_in_kernel(const float* __restrict__ hall, const float* __restrict__ tab,
                              const int* __restrict__ spk, float* __restrict__ cin) {
    int i = blockIdx.x * blockDim.x + threadIdx.x;
    if (i < MC_ * 2 * H_) {
        int row = i / (2*H_), j = i % (2*H_);
        int s = row / B_, b = row % B_;
        float v;
        if (j < H_) v = hall[((size_t)b*S_ + s)*H_ + j];
        else        v = tab[((size_t)b*(S_+1) + spk[b*S_ + s])*H_ + (j - H_)];
        cin[i] = v;
    }
}

// ---------------- epilogue ----------------
#define EPI_TOTAL (16384 + 32768 + 835584)
__global__ void epilogue_kernel(float* __restrict__ out, const float* __restrict__ hall,
                                const float* __restrict__ hspk, const int* __restrict__ pres)
{
    long i = (long)blockIdx.x*256 + threadIdx.x;
    if (i >= EPI_TOTAL) return;
    if (i < 16384) { out[OFF_CTXHID + i] = out[OFF_CTXOUT + (size_t)(S_-1)*B_*H_ + i]; return; }
    i -= 16384;
    if (i < 32768) {
        int n = (int)(i >> 8), c = (int)(i & 255);
        int r = n % R_, b = n / R_;
        out[OFF_RESPHID + ((size_t)r*B_ + b)*H_ + c] = hall[(size_t)(NU_ + n)*H_ + c];
        return;
    }
    i -= 32768;
    {
        int ba = (int)(i >> 8);
        int p = pres[ba];
        out[OFF_SPKEMB + i] = p ? hspk[i] : 0.f;
        if ((i & 255) == 0) {
            int a = ba % (S_+1);
            out[OFF_MASK + ba] = (p && a > 0) ? 1.f : 0.f;
        }
    }
}

// ---------------- launch ----------------
extern "C" void kernel_launch(void* const* d_in, const int* in_sizes, int n_in,
                              void* d_out, int out_size)
{
    const int*   context  = (const int*)d_in[0];
    const int*   response = (const int*)d_in[1];
    const int*   spk      = (const int*)d_in[2];
    const float* emb_u    = (const float*)d_in[3];
    const float* emb_r    = (const float*)d_in[4];
    const float* uWih = (const float*)d_in[5];
    const float* uWhh = (const float*)d_in[6];
    const float* ubih = (const float*)d_in[7];
    const float* ubhh = (const float*)d_in[8];
    const float* cWih = (const float*)d_in[9];
    const float* cWhh = (const float*)d_in[10];
    const float* cbih = (const float*)d_in[11];
    const float* cbhh = (const float*)d_in[12];
    const float* rWih = (const float*)d_in[13];
    const float* rWhh = (const float*)d_in[14];
    const float* rbih = (const float*)d_in[15];
    const float* rbhh = (const float*)d_in[16];
    const float* sWih = (const float*)d_in[17];
    const float* sWhh = (const float*)d_in[18];
    const float* sbih = (const float*)d_in[19];
    const float* sbhh = (const float*)d_in[20];
    float* out = (float*)d_out;

    void *p;
    float *tab, *GIu, *GIc, *GIr, *hall, *hc, *hspk, *cin;
    float *WTu_i, *WTc_i, *WTc_h, *WTr_i, *WTs_i, *WTs_h;
    __nv_bfloat16 *h_hi, *h_lo, *Wu_hi, *Wu_lo, *Wr_hi, *Wr_lo;
    int *toku, *tokr, *pres;
    cudaGetSymbolAddress(&p, g_tables); tab  = (float*)p;
    cudaGetSymbolAddress(&p, g_GIu);    GIu  = (float*)p;
    cudaGetSymbolAddress(&p, g_GIc);    GIc  = (float*)p;
    cudaGetSymbolAddress(&p, g_GIr);    GIr  = (float*)p;
    cudaGetSymbolAddress(&p, g_hall);   hall = (float*)p;
    cudaGetSymbolAddress(&p, g_hbf_hi); h_hi = (__nv_bfloat16*)p;
    cudaGetSymbolAddress(&p, g_hbf_lo); h_lo = (__nv_bfloat16*)p;
    cudaGetSymbolAddress(&p, g_hc);     hc   = (float*)p;
    cudaGetSymbolAddress(&p, g_hspk);   hspk = (float*)p;
    cudaGetSymbolAddress(&p, g_ctxin);  cin  = (float*)p;
    cudaGetSymbolAddress(&p, g_WTu_i);  WTu_i = (float*)p;
    cudaGetSymbolAddress(&p, g_WTc_i);  WTc_i = (float*)p;
    cudaGetSymbolAddress(&p, g_WTc_h);  WTc_h = (float*)p;
    cudaGetSymbolAddress(&p, g_WTr_i);  WTr_i = (float*)p;
    cudaGetSymbolAddress(&p, g_WTs_i);  WTs_i = (float*)p;
    cudaGetSymbolAddress(&p, g_WTs_h);  WTs_h = (float*)p;
    cudaGetSymbolAddress(&p, g_Wubf_hi); Wu_hi = (__nv_bfloat16*)p;
    cudaGetSymbolAddress(&p, g_Wubf_lo); Wu_lo = (__nv_bfloat16*)p;
    cudaGetSymbolAddress(&p, g_Wrbf_hi); Wr_hi = (__nv_bfloat16*)p;
    cudaGetSymbolAddress(&p, g_Wrbf_lo); Wr_lo = (__nv_bfloat16*)p;
    cudaGetSymbolAddress(&p, g_toku);   toku = (int*)p;
    cudaGetSymbolAddress(&p, g_tokr);   tokr = (int*)p;
    cudaGetSymbolAddress(&p, g_present); pres = (int*)p;

    cudaFuncSetAttribute(step_mma_kernel, cudaFuncAttributeMaxDynamicSharedMemorySize, SMEM_STEP);

    // 1. prep
    prep_kernel<<<(PREP_TOTAL + 255)/256, 256>>>(
        context, response, spk,
        uWih, uWhh, cWih, cWhh, rWih, rWhh, sWih, sWhh,
        WTu_i, WTc_i, WTc_h, WTr_i, WTs_i, WTs_h,
        Wu_hi, Wu_lo, Wr_hi, Wr_lo,
        toku, tokr, hall, h_hi, h_lo, hc, hspk, pres);

    // 2. fused GEMMs + MT19937
    mega_gemm_kernel<<<7801, 256>>>(emb_u, emb_r, toku, tokr,
                                    WTu_i, ubih, WTr_i, rbih, GIu, GIr, tab);

    // 3. recurrences via smem-staged mma
    for (int t = 0; t < T_; t++)
        step_mma_kernel<<<104, 256, SMEM_STEP>>>(GIu, GIr, hall, h_hi, h_lo,
                                                 Wu_hi, Wu_lo, Wr_hi, Wr_lo,
                                                 ubhh, rbhh, out + OFF_RESPOUT, t);

    // 4. context input + GEMM
    ctx_in_kernel<<<(MC_*2*H_ + 255)/256, 256>>>(hall, tab, spk, cin);
    gemm_ctx_kernel<<<150, 256>>>(cin, WTc_i, cbih, GIc);

    // 5. pipelined ctx + speaker chains
    for (int i = 0; i <= S_; i++)
        step_cs_kernel<<<32, 256>>>(GIc, hc, WTc_h, cbhh, out + OFF_CTXOUT,
                                    hspk, spk, WTs_i, WTs_h, sbih, sbhh, i);

    // 6. epilogue
    epilogue_kernel<<<(EPI_TOTAL + 255)/256, 256>>>(out, hall, hspk, pres);
}